// round 1
// baseline (speedup 1.0000x reference)
#include <cuda_runtime.h>
#include <math.h>

// ---------------- problem constants ----------------
#define BB   2
#define NN   2048
#define KNB  30
#define DN   256
#define DE   128
#define NL   3
#define NFI  12
#define EFI  28
#define MDIM 640          // 2*DN + DE
#define ETOT (BB*NN*KNB)  // 122880
#define EPSF 1e-6f
#define BIGF 1e9f
#define FLTMAX 3.402823466e38f

// ---------------- scratch (static device globals; no allocation) ----------------
__device__ float g_nodeh[BB*NN*DN];      //   4 MB
__device__ float g_edgeh[ETOT*DE];       //  63 MB
__device__ int   g_eidx [ETOT];
__device__ float g_maski[BB*NN];
__device__ float g_maskij[ETOT];
__device__ float g_denom[BB*NN];
__device__ float g_R  [BB*NN*9];
__device__ float g_Xc [BB*NN*3];
__device__ float g_t1 [ETOT*DN];         // 126 MB
__device__ float g_t2 [ETOT*DE];         //  63 MB
__device__ float g_m  [ETOT*DN];         // 126 MB

__device__ __forceinline__ float softplus_f(float x) {
    return fmaxf(x, 0.0f) + log1pf(expf(-fabsf(x)));
}

// ---------------- 1) per-node frame, features, node_h init ----------------
__global__ void frame_kernel(const float* __restrict__ X, const int* __restrict__ C,
                             const float* __restrict__ Wn, const float* __restrict__ bn)
{
    __shared__ float s_feat[8][12];
    __shared__ float s_mask[8];
    int warp = threadIdx.x >> 5;
    int lane = threadIdx.x & 31;
    int nlin = blockIdx.x * 8 + warp;   // b*NN + n

    if (lane == 0) {
        const float* xr = X + (size_t)nlin * 12;
        float Na[3], CA[3], Ct[3], Oa[3];
        #pragma unroll
        for (int d = 0; d < 3; d++) { Na[d]=xr[d]; CA[d]=xr[3+d]; Ct[d]=xr[6+d]; Oa[d]=xr[9+d]; }
        // centroid: match jnp mean order exactly (rn, no fma)
        #pragma unroll
        for (int d = 0; d < 3; d++) {
            float s = __fadd_rn(__fadd_rn(__fadd_rn(Na[d], CA[d]), Ct[d]), Oa[d]);
            g_Xc[nlin*3 + d] = __fmul_rn(s, 0.25f);
        }
        float b1[3], b2[3], b3[3], v0[3];
        #pragma unroll
        for (int d = 0; d < 3; d++) {
            b1[d] = CA[d] - Na[d];
            b2[d] = Ct[d] - CA[d];
            b3[d] = Oa[d] - Ct[d];
            v0[d] = Na[d] - CA[d];
        }
        float nb2 = sqrtf(b2[0]*b2[0] + b2[1]*b2[1] + b2[2]*b2[2]);
        float u[3];
        #pragma unroll
        for (int d = 0; d < 3; d++) u[d] = b2[d] / (nb2 + EPSF);
        float dotv = v0[0]*u[0] + v0[1]*u[1] + v0[2]*u[2];
        float t[3];
        #pragma unroll
        for (int d = 0; d < 3; d++) t[d] = v0[d] - dotv * u[d];
        float nt = sqrtf(t[0]*t[0] + t[1]*t[1] + t[2]*t[2]);
        float v[3];
        #pragma unroll
        for (int d = 0; d < 3; d++) v[d] = t[d] / (nt + EPSF);
        float w[3];
        w[0] = u[1]*v[2] - u[2]*v[1];
        w[1] = u[2]*v[0] - u[0]*v[2];
        w[2] = u[0]*v[1] - u[1]*v[0];
        #pragma unroll
        for (int d = 0; d < 3; d++) {
            g_R[nlin*9 + d*3 + 0] = u[d];
            g_R[nlin*9 + d*3 + 1] = v[d];
            g_R[nlin*9 + d*3 + 2] = w[d];
        }
        float nb1 = sqrtf(b1[0]*b1[0] + b1[1]*b1[1] + b1[2]*b1[2]);
        float nb3 = sqrtf(b3[0]*b3[0] + b3[1]*b3[1] + b3[2]*b3[2]);
        #pragma unroll
        for (int d = 0; d < 3; d++) {
            s_feat[warp][0 + d] = b1[d] / (nb1 + EPSF);
            s_feat[warp][4 + d] = b2[d] / (nb2 + EPSF);
            s_feat[warp][8 + d] = b3[d] / (nb3 + EPSF);
        }
        s_feat[warp][3]  = logf(nb1 + EPSF);
        s_feat[warp][7]  = logf(nb2 + EPSF);
        s_feat[warp][11] = logf(nb3 + EPSF);
        float mk = (C[nlin] > 0) ? 1.0f : 0.0f;
        s_mask[warp] = mk;
        g_maski[nlin] = mk;
    }
    __syncwarp();

    float f[12];
    #pragma unroll
    for (int i = 0; i < 12; i++) f[i] = s_feat[warp][i];
    float mk = s_mask[warp];
    #pragma unroll
    for (int r = 0; r < 8; r++) {
        int c = lane + r * 32;
        float acc = bn[c];
        #pragma unroll
        for (int ff = 0; ff < NFI; ff++) acc += f[ff] * Wn[ff*DN + c];
        g_nodeh[(size_t)nlin*DN + c] = acc * mk;
    }
}

// ---------------- 2) kNN: exact D2, exact top-k semantics ----------------
__global__ void knn_kernel(const int* __restrict__ C)
{
    __shared__ float s_xc[NN*3];
    __shared__ float s_d2[NN];
    __shared__ float s_rv[256];
    __shared__ int   s_ri[256];

    int nlin = blockIdx.x;
    int b = nlin >> 11;          // / NN
    int n = nlin & (NN - 1);
    int tid = threadIdx.x;

    for (int idx = tid; idx < NN*3; idx += 256)
        s_xc[idx] = g_Xc[(size_t)(b*NN)*3 + idx];
    __syncthreads();

    float xi0 = s_xc[n*3+0], xi1 = s_xc[n*3+1], xi2 = s_xc[n*3+2];
    for (int j = tid; j < NN; j += 256) {
        float dx = __fadd_rn(xi0, -s_xc[j*3+0]);
        float dy = __fadd_rn(xi1, -s_xc[j*3+1]);
        float dz = __fadd_rn(xi2, -s_xc[j*3+2]);
        float d2 = __fadd_rn(__fadd_rn(__fmul_rn(dx,dx), __fmul_rn(dy,dy)), __fmul_rn(dz,dz));
        if (C[b*NN + j] <= 0) d2 = __fadd_rn(d2, BIGF);
        if (j == n)           d2 = __fadd_rn(d2, BIGF);
        s_d2[j] = d2;
    }
    __syncthreads();

    float mi = g_maski[nlin];
    float denom = 0.0f;
    for (int kk = 0; kk < KNB; kk++) {
        float bv = FLTMAX; int bi = 0x7fffffff;
        for (int j = tid; j < NN; j += 256) {
            float v = s_d2[j];
            if (v < bv || (v == bv && j < bi)) { bv = v; bi = j; }
        }
        s_rv[tid] = bv; s_ri[tid] = bi;
        __syncthreads();
        #pragma unroll
        for (int s = 128; s > 0; s >>= 1) {
            if (tid < s) {
                float v2 = s_rv[tid+s]; int i2 = s_ri[tid+s];
                if (v2 < s_rv[tid] || (v2 == s_rv[tid] && i2 < s_ri[tid])) {
                    s_rv[tid] = v2; s_ri[tid] = i2;
                }
            }
            __syncthreads();
        }
        int jsel = s_ri[0];
        if (tid == 0) {
            int e = nlin*KNB + kk;
            g_eidx[e] = jsel;
            float mj = (C[b*NN + jsel] > 0) ? 1.0f : 0.0f;
            float mij = mi * mj;
            g_maskij[e] = mij;
            denom += mij;
            s_d2[jsel] = FLTMAX;
        }
        __syncthreads();
    }
    if (tid == 0) g_denom[nlin] = denom + EPSF;
}

// ---------------- 3) edge features + edge_h init (28 -> 128) ----------------
__global__ void edge_feat_kernel(const float* __restrict__ We, const float* __restrict__ be)
{
    __shared__ float s_feat[KNB][EFI];
    int nlin = blockIdx.x;
    int b = nlin >> 11;
    int tid = threadIdx.x;

    if (tid < KNB) {
        int e = nlin*KNB + tid;
        int j = g_eidx[e];
        int jl = b*NN + j;
        float dv[3];
        #pragma unroll
        for (int d = 0; d < 3; d++) dv[d] = g_Xc[jl*3+d] - g_Xc[nlin*3+d];
        float dist = sqrtf(dv[0]*dv[0] + dv[1]*dv[1] + dv[2]*dv[2]);
        float Ri[9], Rj[9];
        #pragma unroll
        for (int q = 0; q < 9; q++) { Ri[q] = g_R[nlin*9+q]; Rj[q] = g_R[jl*9+q]; }
        float inv = 1.0f / (dist + EPSF);
        #pragma unroll
        for (int c = 0; c < 3; c++) {
            float loc = Ri[0*3+c]*dv[0] + Ri[1*3+c]*dv[1] + Ri[2*3+c]*dv[2];
            s_feat[tid][16 + c] = loc * inv;
        }
        #pragma unroll
        for (int ee = 0; ee < 3; ee++)
            #pragma unroll
            for (int ff = 0; ff < 3; ff++) {
                float r = Ri[0*3+ee]*Rj[0*3+ff] + Ri[1*3+ee]*Rj[1*3+ff] + Ri[2*3+ee]*Rj[2*3+ff];
                s_feat[tid][19 + ee*3 + ff] = r;
            }
        #pragma unroll
        for (int mc = 0; mc < 16; mc++) {
            float cm = (float)(20.0 * mc / 15.0);
            float z = (dist - cm) * 0.8f;   // / 1.25
            s_feat[tid][mc] = expf(-z*z);
        }
    }
    __syncthreads();

    for (int idx = tid; idx < KNB*DE; idx += blockDim.x) {
        int k = idx >> 7;
        int c = idx & 127;
        int e = nlin*KNB + k;
        float acc = be[c];
        #pragma unroll
        for (int f = 0; f < EFI; f++) acc += s_feat[k][f] * We[f*DE + c];
        g_edgeh[(size_t)e*DE + c] = acc * g_maskij[e];
    }
}

// ---------------- 4) tiled fp32 GEMM (128x128x8), A-gather fused ----------------
// GATHER=true : A row e = [node_h[i] | node_h[edge_idx[e]] | edge_h[e]]  (KDIM=640)
// MODE 0: out = softplus(A@W + b)            -> g_t1 (NOUT=256) / g_t2 (NOUT=128)
// MODE 1: out = (A@W + b) * maskij[row]      -> g_m   (A = g_t1)
// MODE 2: edge_h = (edge_h + A@W + b)*maskij           (A = g_t2)
template<int KDIM, int NOUT, bool GATHER, int MODE>
__global__ __launch_bounds__(256) void gemm_kernel(const float* __restrict__ W,
                                                   const float* __restrict__ bias)
{
    constexpr int BM = 128, BN = 128, BK = 8;
    __shared__ __align__(16) float As[BK][BM];
    __shared__ __align__(16) float Bs[BK][BN];
    __shared__ int sOffI[BM], sOffJ[BM];

    const int rowBase = blockIdx.x * BM;
    const int n0 = blockIdx.y * BN;
    const int tid = threadIdx.x;

    if (GATHER) {
        for (int r = tid; r < BM; r += 256) {
            int e = rowBase + r;
            int nlin = e / KNB;
            int b = nlin >> 11;
            int j = g_eidx[e];
            sOffI[r] = nlin * DN;
            sOffJ[r] = (b*NN + j) * DN;
        }
        __syncthreads();
    }

    const float* Aptr = GATHER ? nullptr : (MODE == 1 ? g_t1 : g_t2);

    float acc[8][8];
    #pragma unroll
    for (int i = 0; i < 8; i++)
        #pragma unroll
        for (int j = 0; j < 8; j++) acc[i][j] = 0.0f;

    const int mA = tid >> 1;            // A-load row
    const int kbA = (tid & 1) * 4;      // A-load k offset
    const int kB  = tid >> 5;           // B-load k (tid*4/128)
    const int nB  = (tid & 31) * 4;     // B-load col
    const int ty = tid >> 4;            // compute row group
    const int tx = tid & 15;            // compute col group

    #pragma unroll 1
    for (int k0 = 0; k0 < KDIM; k0 += BK) {
        const float* srcA;
        if (GATHER) {
            if (k0 < DN)            srcA = g_nodeh + sOffI[mA] + k0 + kbA;
            else if (k0 < 2*DN)     srcA = g_nodeh + sOffJ[mA] + (k0 - DN) + kbA;
            else                    srcA = g_edgeh + (size_t)(rowBase + mA)*DE + (k0 - 2*DN) + kbA;
        } else {
            srcA = Aptr + (size_t)(rowBase + mA)*KDIM + k0 + kbA;
        }
        float4 av = *(const float4*)srcA;
        As[kbA+0][mA] = av.x; As[kbA+1][mA] = av.y;
        As[kbA+2][mA] = av.z; As[kbA+3][mA] = av.w;

        float4 bv = *(const float4*)(W + (size_t)(k0 + kB)*NOUT + n0 + nB);
        *(float4*)&Bs[kB][nB] = bv;
        __syncthreads();

        #pragma unroll
        for (int k = 0; k < BK; k++) {
            float4 a0 = *(const float4*)&As[k][ty*8];
            float4 a1 = *(const float4*)&As[k][ty*8+4];
            float4 b0 = *(const float4*)&Bs[k][tx*8];
            float4 b1 = *(const float4*)&Bs[k][tx*8+4];
            float a[8] = {a0.x,a0.y,a0.z,a0.w,a1.x,a1.y,a1.z,a1.w};
            float bb[8] = {b0.x,b0.y,b0.z,b0.w,b1.x,b1.y,b1.z,b1.w};
            #pragma unroll
            for (int i = 0; i < 8; i++)
                #pragma unroll
                for (int j = 0; j < 8; j++)
                    acc[i][j] += a[i] * bb[j];
        }
        __syncthreads();
    }

    #pragma unroll
    for (int i = 0; i < 8; i++) {
        int row = rowBase + ty*8 + i;
        float mij = (MODE != 0) ? g_maskij[row] : 0.0f;
        #pragma unroll
        for (int j = 0; j < 8; j++) {
            int c = n0 + tx*8 + j;
            float v = acc[i][j] + bias[c];
            if (MODE == 0) {
                v = softplus_f(v);
                float* outp = (NOUT == DN) ? g_t1 : g_t2;
                outp[(size_t)row*NOUT + c] = v;
            } else if (MODE == 1) {
                g_m[(size_t)row*NOUT + c] = v * mij;
            } else {
                size_t idx = (size_t)row*DE + c;
                g_edgeh[idx] = (g_edgeh[idx] + v) * mij;
            }
        }
    }
}

// ---------------- 5) node update: node_h = (node_h + sum_k m / denom) * mask_i ----------------
__global__ void node_update_kernel()
{
    int nlin = blockIdx.x;
    int c = threadIdx.x;
    float sum = 0.0f;
    #pragma unroll
    for (int k = 0; k < KNB; k++)
        sum += g_m[(size_t)(nlin*KNB + k)*DN + c];
    float val = (g_nodeh[(size_t)nlin*DN + c] + sum / g_denom[nlin]) * g_maski[nlin];
    g_nodeh[(size_t)nlin*DN + c] = val;
}

// ---------------- 6) pack outputs ----------------
__global__ void copy_out_kernel(float* __restrict__ out)
{
    const int S0 = BB*NN*DN;               // node_h
    const int S1 = ETOT*DE;                // edge_h
    const int S2 = ETOT;                   // edge_idx
    const int S3 = BB*NN;                  // mask_i
    const int TOT = S0 + S1 + S2 + S3 + ETOT;
    for (int i = blockIdx.x*blockDim.x + threadIdx.x; i < TOT; i += gridDim.x*blockDim.x) {
        float v;
        if (i < S0)                    v = g_nodeh[i];
        else if (i < S0+S1)            v = g_edgeh[i - S0];
        else if (i < S0+S1+S2)         v = (float)g_eidx[i - S0 - S1];
        else if (i < S0+S1+S2+S3)      v = g_maski[i - S0 - S1 - S2];
        else                           v = g_maskij[i - S0 - S1 - S2 - S3];
        out[i] = v;
    }
}

// ---------------- launch ----------------
extern "C" void kernel_launch(void* const* d_in, const int* in_sizes, int n_in,
                              void* d_out, int out_size)
{
    const float* X    = (const float*)d_in[0];
    const int*   C    = (const int*)  d_in[1];
    const float* Wn   = (const float*)d_in[2];
    const float* bn   = (const float*)d_in[3];
    const float* We   = (const float*)d_in[4];
    const float* be   = (const float*)d_in[5];
    const float* Wm1  = (const float*)d_in[6];
    const float* bm1  = (const float*)d_in[7];
    const float* Wm2  = (const float*)d_in[8];
    const float* bm2  = (const float*)d_in[9];
    const float* Wue1 = (const float*)d_in[10];
    const float* bue1 = (const float*)d_in[11];
    const float* Wue2 = (const float*)d_in[12];
    const float* bue2 = (const float*)d_in[13];

    frame_kernel<<<BB*NN/8, 256>>>(X, C, Wn, bn);
    knn_kernel<<<BB*NN, 256>>>(C);
    edge_feat_kernel<<<BB*NN, 128>>>(We, be);

    const dim3 gv1a(ETOT/128, DN/128);   // (960, 2)
    const dim3 gv1b(ETOT/128, DE/128);   // (960, 1)

    for (int l = 0; l < NL; l++) {
        gemm_kernel<MDIM, DN, true, 0><<<gv1a, 256>>>(Wm1  + (size_t)l*MDIM*DN, bm1  + l*DN);
        gemm_kernel<MDIM, DE, true, 0><<<gv1b, 256>>>(Wue1 + (size_t)l*MDIM*DE, bue1 + l*DE);
        gemm_kernel<DN,   DN, false,1><<<gv1a, 256>>>(Wm2  + (size_t)l*DN*DN,   bm2  + l*DN);
        node_update_kernel<<<BB*NN, DN>>>();
        gemm_kernel<DE,   DE, false,2><<<gv1b, 256>>>(Wue2 + (size_t)l*DE*DE,   bue2 + l*DE);
    }

    copy_out_kernel<<<16384, 256>>>((float*)d_out);
}

// round 2
// speedup vs baseline: 1.7052x; 1.7052x over previous
#include <cuda_runtime.h>
#include <math.h>

// ---------------- problem constants ----------------
#define BB   2
#define NN   2048
#define KNB  30
#define DN   256
#define DE   128
#define NL   3
#define NFI  12
#define EFI  28
#define ETOT (BB*NN*KNB)  // 122880
#define NNODE (BB*NN)     // 4096
#define EPSF 1e-6f
#define BIGF 1e9f
#define FLTMAX 3.402823466e38f

// ---------------- scratch ----------------
__device__ float g_nodeh[NNODE*DN];        //   4 MB
__device__ float g_edgeh[ETOT*DE];         //  63 MB
__device__ int   g_eidx [ETOT];
__device__ float g_maski[NNODE];
__device__ float g_maskij[ETOT];
__device__ float g_denom[NNODE];
__device__ float g_cnt  [NNODE];
__device__ float g_R  [NNODE*9];
__device__ float g_Xc [NNODE*3];
__device__ float g_t1 [ETOT*DN];           // 126 MB  softplus(m-path)
__device__ float g_t2 [ETOT*DE];           //  63 MB  softplus(e-path)
__device__ float g_Ym [2*NNODE*DN];        //   8 MB  [Yi_m | Zj_m]
__device__ float g_Ye [2*NNODE*DE];        //   4 MB  [Yi_e | Zj_e]
__device__ float g_ksum[NNODE*DN];         //   4 MB

__device__ __forceinline__ float softplus_f(float x) {
    return fmaxf(x, 0.0f) + log1pf(expf(-fabsf(x)));
}

// ---------------- 1) per-node frame, features, node_h init ----------------
__global__ void frame_kernel(const float* __restrict__ X, const int* __restrict__ C,
                             const float* __restrict__ Wn, const float* __restrict__ bn)
{
    __shared__ float s_feat[8][12];
    __shared__ float s_mask[8];
    int warp = threadIdx.x >> 5;
    int lane = threadIdx.x & 31;
    int nlin = blockIdx.x * 8 + warp;

    if (lane == 0) {
        const float* xr = X + (size_t)nlin * 12;
        float Na[3], CA[3], Ct[3], Oa[3];
        #pragma unroll
        for (int d = 0; d < 3; d++) { Na[d]=xr[d]; CA[d]=xr[3+d]; Ct[d]=xr[6+d]; Oa[d]=xr[9+d]; }
        #pragma unroll
        for (int d = 0; d < 3; d++) {
            float s = __fadd_rn(__fadd_rn(__fadd_rn(Na[d], CA[d]), Ct[d]), Oa[d]);
            g_Xc[nlin*3 + d] = __fmul_rn(s, 0.25f);
        }
        float b1[3], b2[3], b3[3], v0[3];
        #pragma unroll
        for (int d = 0; d < 3; d++) {
            b1[d] = CA[d] - Na[d];
            b2[d] = Ct[d] - CA[d];
            b3[d] = Oa[d] - Ct[d];
            v0[d] = Na[d] - CA[d];
        }
        float nb2 = sqrtf(b2[0]*b2[0] + b2[1]*b2[1] + b2[2]*b2[2]);
        float u[3];
        #pragma unroll
        for (int d = 0; d < 3; d++) u[d] = b2[d] / (nb2 + EPSF);
        float dotv = v0[0]*u[0] + v0[1]*u[1] + v0[2]*u[2];
        float t[3];
        #pragma unroll
        for (int d = 0; d < 3; d++) t[d] = v0[d] - dotv * u[d];
        float nt = sqrtf(t[0]*t[0] + t[1]*t[1] + t[2]*t[2]);
        float v[3];
        #pragma unroll
        for (int d = 0; d < 3; d++) v[d] = t[d] / (nt + EPSF);
        float w[3];
        w[0] = u[1]*v[2] - u[2]*v[1];
        w[1] = u[2]*v[0] - u[0]*v[2];
        w[2] = u[0]*v[1] - u[1]*v[0];
        #pragma unroll
        for (int d = 0; d < 3; d++) {
            g_R[nlin*9 + d*3 + 0] = u[d];
            g_R[nlin*9 + d*3 + 1] = v[d];
            g_R[nlin*9 + d*3 + 2] = w[d];
        }
        float nb1 = sqrtf(b1[0]*b1[0] + b1[1]*b1[1] + b1[2]*b1[2]);
        float nb3 = sqrtf(b3[0]*b3[0] + b3[1]*b3[1] + b3[2]*b3[2]);
        #pragma unroll
        for (int d = 0; d < 3; d++) {
            s_feat[warp][0 + d] = b1[d] / (nb1 + EPSF);
            s_feat[warp][4 + d] = b2[d] / (nb2 + EPSF);
            s_feat[warp][8 + d] = b3[d] / (nb3 + EPSF);
        }
        s_feat[warp][3]  = logf(nb1 + EPSF);
        s_feat[warp][7]  = logf(nb2 + EPSF);
        s_feat[warp][11] = logf(nb3 + EPSF);
        float mk = (C[nlin] > 0) ? 1.0f : 0.0f;
        s_mask[warp] = mk;
        g_maski[nlin] = mk;
    }
    __syncwarp();

    float f[12];
    #pragma unroll
    for (int i = 0; i < 12; i++) f[i] = s_feat[warp][i];
    float mk = s_mask[warp];
    #pragma unroll
    for (int r = 0; r < 8; r++) {
        int c = lane + r * 32;
        float acc = bn[c];
        #pragma unroll
        for (int ff = 0; ff < NFI; ff++) acc += f[ff] * Wn[ff*DN + c];
        g_nodeh[(size_t)nlin*DN + c] = acc * mk;
    }
}

// ---------------- 2) kNN ----------------
__global__ void knn_kernel(const int* __restrict__ C)
{
    __shared__ float s_xc[NN*3];
    __shared__ float s_d2[NN];
    __shared__ float s_rv[256];
    __shared__ int   s_ri[256];

    int nlin = blockIdx.x;
    int b = nlin >> 11;
    int n = nlin & (NN - 1);
    int tid = threadIdx.x;

    for (int idx = tid; idx < NN*3; idx += 256)
        s_xc[idx] = g_Xc[(size_t)(b*NN)*3 + idx];
    __syncthreads();

    float xi0 = s_xc[n*3+0], xi1 = s_xc[n*3+1], xi2 = s_xc[n*3+2];
    for (int j = tid; j < NN; j += 256) {
        float dx = __fadd_rn(xi0, -s_xc[j*3+0]);
        float dy = __fadd_rn(xi1, -s_xc[j*3+1]);
        float dz = __fadd_rn(xi2, -s_xc[j*3+2]);
        float d2 = __fadd_rn(__fadd_rn(__fmul_rn(dx,dx), __fmul_rn(dy,dy)), __fmul_rn(dz,dz));
        if (C[b*NN + j] <= 0) d2 = __fadd_rn(d2, BIGF);
        if (j == n)           d2 = __fadd_rn(d2, BIGF);
        s_d2[j] = d2;
    }
    __syncthreads();

    float mi = g_maski[nlin];
    float cnt = 0.0f;
    for (int kk = 0; kk < KNB; kk++) {
        float bv = FLTMAX; int bi = 0x7fffffff;
        for (int j = tid; j < NN; j += 256) {
            float v = s_d2[j];
            if (v < bv || (v == bv && j < bi)) { bv = v; bi = j; }
        }
        s_rv[tid] = bv; s_ri[tid] = bi;
        __syncthreads();
        #pragma unroll
        for (int s = 128; s > 0; s >>= 1) {
            if (tid < s) {
                float v2 = s_rv[tid+s]; int i2 = s_ri[tid+s];
                if (v2 < s_rv[tid] || (v2 == s_rv[tid] && i2 < s_ri[tid])) {
                    s_rv[tid] = v2; s_ri[tid] = i2;
                }
            }
            __syncthreads();
        }
        int jsel = s_ri[0];
        if (tid == 0) {
            int e = nlin*KNB + kk;
            g_eidx[e] = jsel;
            float mj = (C[b*NN + jsel] > 0) ? 1.0f : 0.0f;
            float mij = mi * mj;
            g_maskij[e] = mij;
            cnt += mij;
            s_d2[jsel] = FLTMAX;
        }
        __syncthreads();
    }
    if (tid == 0) { g_cnt[nlin] = cnt; g_denom[nlin] = cnt + EPSF; }
}

// ---------------- 3) edge features + edge_h init ----------------
__global__ void edge_feat_kernel(const float* __restrict__ We, const float* __restrict__ be)
{
    __shared__ float s_feat[KNB][EFI];
    int nlin = blockIdx.x;
    int b = nlin >> 11;
    int tid = threadIdx.x;

    if (tid < KNB) {
        int e = nlin*KNB + tid;
        int j = g_eidx[e];
        int jl = b*NN + j;
        float dv[3];
        #pragma unroll
        for (int d = 0; d < 3; d++) dv[d] = g_Xc[jl*3+d] - g_Xc[nlin*3+d];
        float dist = sqrtf(dv[0]*dv[0] + dv[1]*dv[1] + dv[2]*dv[2]);
        float Ri[9], Rj[9];
        #pragma unroll
        for (int q = 0; q < 9; q++) { Ri[q] = g_R[nlin*9+q]; Rj[q] = g_R[jl*9+q]; }
        float inv = 1.0f / (dist + EPSF);
        #pragma unroll
        for (int c = 0; c < 3; c++) {
            float loc = Ri[0*3+c]*dv[0] + Ri[1*3+c]*dv[1] + Ri[2*3+c]*dv[2];
            s_feat[tid][16 + c] = loc * inv;
        }
        #pragma unroll
        for (int ee = 0; ee < 3; ee++)
            #pragma unroll
            for (int ff = 0; ff < 3; ff++) {
                float r = Ri[0*3+ee]*Rj[0*3+ff] + Ri[1*3+ee]*Rj[1*3+ff] + Ri[2*3+ee]*Rj[2*3+ff];
                s_feat[tid][19 + ee*3 + ff] = r;
            }
        #pragma unroll
        for (int mc = 0; mc < 16; mc++) {
            float cm = (float)(20.0 * mc / 15.0);
            float z = (dist - cm) * 0.8f;
            s_feat[tid][mc] = expf(-z*z);
        }
    }
    __syncthreads();

    for (int idx = tid; idx < KNB*DE; idx += blockDim.x) {
        int k = idx >> 7;
        int c = idx & 127;
        int e = nlin*KNB + k;
        float acc = be[c];
        #pragma unroll
        for (int f = 0; f < EFI; f++) acc += s_feat[k][f] * We[f*DE + c];
        g_edgeh[(size_t)e*DE + c] = acc * g_maskij[e];
    }
}

// ---------------- 4) edge GEMM: M=122880, K=128, double-buffered ----------------
// MODE 0: out = softplus(A@W + bias + Yi[i] + Zj[j])     (A = edge_h)
// MODE 2: out(edge_h) = (edge_h + A@W + bias) * maskij   (A = t2)
template<int NOUT, int MODE>
__global__ __launch_bounds__(256) void edge_gemm(
    const float* __restrict__ A, const float* __restrict__ W,
    const float* __restrict__ bias,
    const float* __restrict__ Yi, const float* __restrict__ Zj,
    float* __restrict__ out)
{
    constexpr int BM = 128, BN = 128, BK = 8, KD = 128;
    __shared__ __align__(16) float As[2][BK][BM];
    __shared__ __align__(16) float Bs[2][BK][BN];
    __shared__ int sI[BM], sJ[BM];

    const int rowBase = blockIdx.x * BM;
    const int n0 = blockIdx.y * BN;
    const int tid = threadIdx.x;

    if (MODE == 0) {
        for (int r = tid; r < BM; r += 256) {
            int e = rowBase + r;
            int nlin = e / KNB;
            int b = nlin >> 11;
            sI[r] = nlin * NOUT;
            sJ[r] = (b*NN + g_eidx[e]) * NOUT;
        }
    }

    const int mA = tid >> 1, kbA = (tid & 1) * 4;
    const int kB = tid >> 5, nB = (tid & 31) * 4;
    const int ty = tid >> 4, tx = tid & 15;

    // preload tile 0
    {
        float4 av = *(const float4*)(A + (size_t)(rowBase+mA)*KD + kbA);
        float4 bv = *(const float4*)(W + (size_t)kB*NOUT + n0 + nB);
        As[0][kbA+0][mA]=av.x; As[0][kbA+1][mA]=av.y;
        As[0][kbA+2][mA]=av.z; As[0][kbA+3][mA]=av.w;
        *(float4*)&Bs[0][kB][nB] = bv;
    }
    __syncthreads();

    float acc[8][8];
    #pragma unroll
    for (int i = 0; i < 8; i++)
        #pragma unroll
        for (int j = 0; j < 8; j++) acc[i][j] = 0.0f;

    int buf = 0;
    #pragma unroll 1
    for (int t = 0; t < KD/BK; t++) {
        float4 pav, pbv;
        if (t + 1 < KD/BK) {
            pav = *(const float4*)(A + (size_t)(rowBase+mA)*KD + (t+1)*BK + kbA);
            pbv = *(const float4*)(W + (size_t)((t+1)*BK + kB)*NOUT + n0 + nB);
        }
        #pragma unroll
        for (int k = 0; k < BK; k++) {
            float4 a0 = *(const float4*)&As[buf][k][ty*8];
            float4 a1 = *(const float4*)&As[buf][k][ty*8+4];
            float4 b0 = *(const float4*)&Bs[buf][k][tx*8];
            float4 b1 = *(const float4*)&Bs[buf][k][tx*8+4];
            float a[8]  = {a0.x,a0.y,a0.z,a0.w,a1.x,a1.y,a1.z,a1.w};
            float bb[8] = {b0.x,b0.y,b0.z,b0.w,b1.x,b1.y,b1.z,b1.w};
            #pragma unroll
            for (int i = 0; i < 8; i++)
                #pragma unroll
                for (int j = 0; j < 8; j++)
                    acc[i][j] += a[i] * bb[j];
        }
        if (t + 1 < KD/BK) {
            As[buf^1][kbA+0][mA]=pav.x; As[buf^1][kbA+1][mA]=pav.y;
            As[buf^1][kbA+2][mA]=pav.z; As[buf^1][kbA+3][mA]=pav.w;
            *(float4*)&Bs[buf^1][kB][nB] = pbv;
        }
        __syncthreads();
        buf ^= 1;
    }

    float4 bias0 = *(const float4*)(bias + n0 + tx*8);
    float4 bias1 = *(const float4*)(bias + n0 + tx*8 + 4);
    float bs[8] = {bias0.x,bias0.y,bias0.z,bias0.w,bias1.x,bias1.y,bias1.z,bias1.w};

    #pragma unroll
    for (int i = 0; i < 8; i++) {
        int r = ty*8 + i;
        int row = rowBase + r;
        if (MODE == 0) {
            float4 y0 = *(const float4*)(Yi + sI[r] + n0 + tx*8);
            float4 y1 = *(const float4*)(Yi + sI[r] + n0 + tx*8 + 4);
            float4 z0 = *(const float4*)(Zj + sJ[r] + n0 + tx*8);
            float4 z1 = *(const float4*)(Zj + sJ[r] + n0 + tx*8 + 4);
            float yv[8] = {y0.x,y0.y,y0.z,y0.w,y1.x,y1.y,y1.z,y1.w};
            float zv[8] = {z0.x,z0.y,z0.z,z0.w,z1.x,z1.y,z1.z,z1.w};
            #pragma unroll
            for (int j = 0; j < 8; j++) {
                int c = n0 + tx*8 + j;
                float v = acc[i][j] + bs[j] + yv[j] + zv[j];
                out[(size_t)row*NOUT + c] = softplus_f(v);
            }
        } else {
            float mij = g_maskij[row];
            #pragma unroll
            for (int j = 0; j < 8; j++) {
                int c = n0 + tx*8 + j;
                size_t idx = (size_t)row*NOUT + c;
                out[idx] = (g_edgeh[idx] + acc[i][j] + bs[j]) * mij;
            }
        }
    }
}

// ---------------- 5) node-side GEMM: M=4096, K=256, BM=128 BN=64 ----------------
// MODE 0: out[z] = A @ W[z]              (raw, no bias; z = blockIdx.z selects B slab)
// MODE 1: node_h = (node_h + (A@W + cnt*bias)/denom) * mask_i
template<int NOUT, int MODE>
__global__ __launch_bounds__(256) void node_gemm(
    const float* __restrict__ A, const float* __restrict__ Wbase,
    const float* __restrict__ bias, float* __restrict__ outbase)
{
    constexpr int BM = 128, BN = 64, BK = 16, KD = 256;
    __shared__ __align__(16) float As[2][BK][BM];
    __shared__ __align__(16) float Bs[2][BK][BN];

    const int rowBase = blockIdx.x * BM;
    const int n0 = blockIdx.y * BN;
    const int z = blockIdx.z;
    const float* W = Wbase + (size_t)z * KD * NOUT;
    float* out = (MODE == 0) ? (outbase + (size_t)z * NNODE * NOUT) : outbase;
    const int tid = threadIdx.x;

    // A tile: 128x16 = 512 float4, 2 per thread
    const int l0 = tid * 2;
    const int rA0 = l0 >> 2,        kA0 = (l0 & 3) * 4;
    const int rA1 = (l0 + 1) >> 2,  kA1 = ((l0 + 1) & 3) * 4;
    // B tile: 16x64 = 256 float4, 1 per thread
    const int kB = tid >> 4, nB = (tid & 15) * 4;
    const int ty = tid >> 4, tx = tid & 15;

    {
        float4 a0 = *(const float4*)(A + (size_t)(rowBase+rA0)*KD + kA0);
        float4 a1 = *(const float4*)(A + (size_t)(rowBase+rA1)*KD + kA1);
        float4 bv = *(const float4*)(W + (size_t)kB*NOUT + n0 + nB);
        As[0][kA0+0][rA0]=a0.x; As[0][kA0+1][rA0]=a0.y; As[0][kA0+2][rA0]=a0.z; As[0][kA0+3][rA0]=a0.w;
        As[0][kA1+0][rA1]=a1.x; As[0][kA1+1][rA1]=a1.y; As[0][kA1+2][rA1]=a1.z; As[0][kA1+3][rA1]=a1.w;
        *(float4*)&Bs[0][kB][nB] = bv;
    }
    __syncthreads();

    float acc[8][4];
    #pragma unroll
    for (int i = 0; i < 8; i++)
        #pragma unroll
        for (int j = 0; j < 4; j++) acc[i][j] = 0.0f;

    int buf = 0;
    #pragma unroll 1
    for (int t = 0; t < KD/BK; t++) {
        float4 p0, p1, pb;
        if (t + 1 < KD/BK) {
            p0 = *(const float4*)(A + (size_t)(rowBase+rA0)*KD + (t+1)*BK + kA0);
            p1 = *(const float4*)(A + (size_t)(rowBase+rA1)*KD + (t+1)*BK + kA1);
            pb = *(const float4*)(W + (size_t)((t+1)*BK + kB)*NOUT + n0 + nB);
        }
        #pragma unroll
        for (int k = 0; k < BK; k++) {
            float4 a0 = *(const float4*)&As[buf][k][ty*8];
            float4 a1 = *(const float4*)&As[buf][k][ty*8+4];
            float4 b0 = *(const float4*)&Bs[buf][k][tx*4];
            float a[8]  = {a0.x,a0.y,a0.z,a0.w,a1.x,a1.y,a1.z,a1.w};
            float bb[4] = {b0.x,b0.y,b0.z,b0.w};
            #pragma unroll
            for (int i = 0; i < 8; i++)
                #pragma unroll
                for (int j = 0; j < 4; j++)
                    acc[i][j] += a[i] * bb[j];
        }
        if (t + 1 < KD/BK) {
            As[buf^1][kA0+0][rA0]=p0.x; As[buf^1][kA0+1][rA0]=p0.y; As[buf^1][kA0+2][rA0]=p0.z; As[buf^1][kA0+3][rA0]=p0.w;
            As[buf^1][kA1+0][rA1]=p1.x; As[buf^1][kA1+1][rA1]=p1.y; As[buf^1][kA1+2][rA1]=p1.z; As[buf^1][kA1+3][rA1]=p1.w;
            *(float4*)&Bs[buf^1][kB][nB] = pb;
        }
        __syncthreads();
        buf ^= 1;
    }

    #pragma unroll
    for (int i = 0; i < 8; i++) {
        int row = rowBase + ty*8 + i;
        if (MODE == 0) {
            #pragma unroll
            for (int j = 0; j < 4; j++) {
                int c = n0 + tx*4 + j;
                out[(size_t)row*NOUT + c] = acc[i][j];
            }
        } else {
            float dn = g_denom[row];
            float mi = g_maski[row];
            float cn = g_cnt[row];
            #pragma unroll
            for (int j = 0; j < 4; j++) {
                int c = n0 + tx*4 + j;
                float v = (g_nodeh[(size_t)row*DN + c] + (acc[i][j] + cn*bias[c]) / dn) * mi;
                out[(size_t)row*DN + c] = v;
            }
        }
    }
}

// ---------------- 6) masked k-sum of t1 per node ----------------
__global__ void ksum_kernel()
{
    __shared__ float sm[KNB];
    int nlin = blockIdx.x;
    int c = threadIdx.x;
    if (c < KNB) sm[c] = g_maskij[nlin*KNB + c];
    __syncthreads();
    float s = 0.0f;
    #pragma unroll
    for (int k = 0; k < KNB; k++)
        s += sm[k] * g_t1[(size_t)(nlin*KNB + k)*DN + c];
    g_ksum[(size_t)nlin*DN + c] = s;
}

// ---------------- 7) pack outputs ----------------
__global__ void copy_out_kernel(float* __restrict__ out)
{
    const int S0 = NNODE*DN;
    const int S1 = ETOT*DE;
    const int S2 = ETOT;
    const int S3 = NNODE;
    const int TOT = S0 + S1 + S2 + S3 + ETOT;
    for (int i = blockIdx.x*blockDim.x + threadIdx.x; i < TOT; i += gridDim.x*blockDim.x) {
        float v;
        if (i < S0)                    v = g_nodeh[i];
        else if (i < S0+S1)            v = g_edgeh[i - S0];
        else if (i < S0+S1+S2)         v = (float)g_eidx[i - S0 - S1];
        else if (i < S0+S1+S2+S3)      v = g_maski[i - S0 - S1 - S2];
        else                           v = g_maskij[i - S0 - S1 - S2 - S3];
        out[i] = v;
    }
}

// ---------------- launch ----------------
extern "C" void kernel_launch(void* const* d_in, const int* in_sizes, int n_in,
                              void* d_out, int out_size)
{
    const float* X    = (const float*)d_in[0];
    const int*   C    = (const int*)  d_in[1];
    const float* Wn   = (const float*)d_in[2];
    const float* bn   = (const float*)d_in[3];
    const float* We   = (const float*)d_in[4];
    const float* be   = (const float*)d_in[5];
    const float* Wm1  = (const float*)d_in[6];
    const float* bm1  = (const float*)d_in[7];
    const float* Wm2  = (const float*)d_in[8];
    const float* bm2  = (const float*)d_in[9];
    const float* Wue1 = (const float*)d_in[10];
    const float* bue1 = (const float*)d_in[11];
    const float* Wue2 = (const float*)d_in[12];
    const float* bue2 = (const float*)d_in[13];

    frame_kernel<<<NNODE/8, 256>>>(X, C, Wn, bn);
    knn_kernel<<<NNODE, 256>>>(C);
    edge_feat_kernel<<<NNODE, 128>>>(We, be);

    // device symbol addresses usable from host launch args (same pointers inside kernels)
    float* Ym; cudaGetSymbolAddress((void**)&Ym, g_Ym);
    float* Ye; cudaGetSymbolAddress((void**)&Ye, g_Ye);
    float* T1; cudaGetSymbolAddress((void**)&T1, g_t1);
    float* T2; cudaGetSymbolAddress((void**)&T2, g_t2);
    float* Eh; cudaGetSymbolAddress((void**)&Eh, g_edgeh);
    float* Nh; cudaGetSymbolAddress((void**)&Nh, g_nodeh);
    float* Ks; cudaGetSymbolAddress((void**)&Ks, g_ksum);

    const int MD = 2*DN + DE;  // 640
    for (int l = 0; l < NL; l++) {
        const float* Wm1l  = Wm1  + (size_t)l*MD*DN;
        const float* Wue1l = Wue1 + (size_t)l*MD*DE;
        // node-side precompute: Yi/Zj for m-path and e-path
        node_gemm<DN, 0><<<dim3(NNODE/128, DN/64, 2), 256>>>(Nh, Wm1l,  Wm1l,  Ym);
        node_gemm<DE, 0><<<dim3(NNODE/128, DE/64, 2), 256>>>(Nh, Wue1l, Wue1l, Ye);
        // edge GEMMs (K=128, e-part of W), fused gather-add + softplus
        edge_gemm<DN, 0><<<dim3(ETOT/128, DN/128), 256>>>(
            Eh, Wm1l  + (size_t)2*DN*DN, bm1  + l*DN, Ym, Ym + NNODE*DN, T1);
        edge_gemm<DE, 0><<<dim3(ETOT/128, DE/128), 256>>>(
            Eh, Wue1l + (size_t)2*DN*DE, bue1 + l*DE, Ye, Ye + NNODE*DE, T2);
        // node update: masked k-sum then small GEMM with fused update
        ksum_kernel<<<NNODE, DN>>>();
        node_gemm<DN, 1><<<dim3(NNODE/128, DN/64, 1), 256>>>(
            Ks, Wm2 + (size_t)l*DN*DN, bm2 + l*DN, Nh);
        // edge update
        edge_gemm<DE, 2><<<dim3(ETOT/128, DE/128), 256>>>(
            T2, Wue2 + (size_t)l*DE*DE, bue2 + l*DE, nullptr, nullptr, Eh);
    }

    copy_out_kernel<<<16384, 256>>>((float*)d_out);
}

// round 3
// speedup vs baseline: 3.7740x; 2.2133x over previous
#include <cuda_runtime.h>
#include <math.h>

// ---------------- problem constants ----------------
#define BB   2
#define NN   2048
#define KNB  30
#define DN   256
#define DE   128
#define NL   3
#define NFI  12
#define EFI  28
#define ETOT (BB*NN*KNB)  // 122880
#define NNODE (BB*NN)     // 4096
#define EPSF 1e-6f
#define BIGF 1e9f
#define FLTMAX 3.402823466e38f

// ---------------- scratch ----------------
__device__ float g_nodeh[NNODE*DN];
__device__ float g_edgeh[ETOT*DE];
__device__ int   g_eidx [ETOT];
__device__ float g_maski[NNODE];
__device__ float g_maskij[ETOT];
__device__ float g_denom[NNODE];
__device__ float g_cnt  [NNODE];
__device__ float g_R  [NNODE*9];
__device__ float g_Xc [NNODE*3];
__device__ float g_t1 [ETOT*DN];
__device__ float g_t2 [ETOT*DE];
__device__ float g_Ym [2*NNODE*DN];
__device__ float g_Ye [2*NNODE*DE];
__device__ float g_ksum[NNODE*DN];

__device__ __forceinline__ float softplus_f(float x) {
    return fmaxf(x, 0.0f) + log1pf(expf(-fabsf(x)));
}
__device__ __forceinline__ unsigned f2tf(float x) {
    unsigned r; asm("cvt.rna.tf32.f32 %0, %1;" : "=r"(r) : "f"(x)); return r;
}
__device__ __forceinline__ void mma8(float* c, const unsigned* a, const unsigned* b) {
    asm volatile(
        "mma.sync.aligned.m16n8k8.row.col.f32.tf32.tf32.f32 "
        "{%0,%1,%2,%3},{%4,%5,%6,%7},{%8,%9},{%0,%1,%2,%3};"
        : "+f"(c[0]), "+f"(c[1]), "+f"(c[2]), "+f"(c[3])
        : "r"(a[0]), "r"(a[1]), "r"(a[2]), "r"(a[3]), "r"(b[0]), "r"(b[1]));
}

// ---------------- 1) per-node frame, features, node_h init ----------------
__global__ void frame_kernel(const float* __restrict__ X, const int* __restrict__ C,
                             const float* __restrict__ Wn, const float* __restrict__ bn)
{
    __shared__ float s_feat[8][12];
    __shared__ float s_mask[8];
    int warp = threadIdx.x >> 5;
    int lane = threadIdx.x & 31;
    int nlin = blockIdx.x * 8 + warp;

    if (lane == 0) {
        const float* xr = X + (size_t)nlin * 12;
        float Na[3], CA[3], Ct[3], Oa[3];
        #pragma unroll
        for (int d = 0; d < 3; d++) { Na[d]=xr[d]; CA[d]=xr[3+d]; Ct[d]=xr[6+d]; Oa[d]=xr[9+d]; }
        #pragma unroll
        for (int d = 0; d < 3; d++) {
            float s = __fadd_rn(__fadd_rn(__fadd_rn(Na[d], CA[d]), Ct[d]), Oa[d]);
            g_Xc[nlin*3 + d] = __fmul_rn(s, 0.25f);
        }
        float b1[3], b2[3], b3[3], v0[3];
        #pragma unroll
        for (int d = 0; d < 3; d++) {
            b1[d] = CA[d] - Na[d];
            b2[d] = Ct[d] - CA[d];
            b3[d] = Oa[d] - Ct[d];
            v0[d] = Na[d] - CA[d];
        }
        float nb2 = sqrtf(b2[0]*b2[0] + b2[1]*b2[1] + b2[2]*b2[2]);
        float u[3];
        #pragma unroll
        for (int d = 0; d < 3; d++) u[d] = b2[d] / (nb2 + EPSF);
        float dotv = v0[0]*u[0] + v0[1]*u[1] + v0[2]*u[2];
        float t[3];
        #pragma unroll
        for (int d = 0; d < 3; d++) t[d] = v0[d] - dotv * u[d];
        float nt = sqrtf(t[0]*t[0] + t[1]*t[1] + t[2]*t[2]);
        float v[3];
        #pragma unroll
        for (int d = 0; d < 3; d++) v[d] = t[d] / (nt + EPSF);
        float w[3];
        w[0] = u[1]*v[2] - u[2]*v[1];
        w[1] = u[2]*v[0] - u[0]*v[2];
        w[2] = u[0]*v[1] - u[1]*v[0];
        #pragma unroll
        for (int d = 0; d < 3; d++) {
            g_R[nlin*9 + d*3 + 0] = u[d];
            g_R[nlin*9 + d*3 + 1] = v[d];
            g_R[nlin*9 + d*3 + 2] = w[d];
        }
        float nb1 = sqrtf(b1[0]*b1[0] + b1[1]*b1[1] + b1[2]*b1[2]);
        float nb3 = sqrtf(b3[0]*b3[0] + b3[1]*b3[1] + b3[2]*b3[2]);
        #pragma unroll
        for (int d = 0; d < 3; d++) {
            s_feat[warp][0 + d] = b1[d] / (nb1 + EPSF);
            s_feat[warp][4 + d] = b2[d] / (nb2 + EPSF);
            s_feat[warp][8 + d] = b3[d] / (nb3 + EPSF);
        }
        s_feat[warp][3]  = logf(nb1 + EPSF);
        s_feat[warp][7]  = logf(nb2 + EPSF);
        s_feat[warp][11] = logf(nb3 + EPSF);
        float mk = (C[nlin] > 0) ? 1.0f : 0.0f;
        s_mask[warp] = mk;
        g_maski[nlin] = mk;
    }
    __syncwarp();

    float f[12];
    #pragma unroll
    for (int i = 0; i < 12; i++) f[i] = s_feat[warp][i];
    float mk = s_mask[warp];
    #pragma unroll
    for (int r = 0; r < 8; r++) {
        int c = lane + r * 32;
        float acc = bn[c];
        #pragma unroll
        for (int ff = 0; ff < NFI; ff++) acc += f[ff] * Wn[ff*DN + c];
        g_nodeh[(size_t)nlin*DN + c] = acc * mk;
    }
}

// ---------------- 2) kNN: warp-per-node, exact semantics ----------------
__global__ __launch_bounds__(128) void knn_kernel(const int* __restrict__ C)
{
    __shared__ float s_d2[4][NN];   // 32 KB
    int wid = threadIdx.x >> 5;
    int lane = threadIdx.x & 31;
    int nlin = blockIdx.x * 4 + wid;
    int b = nlin >> 11;
    int n = nlin & (NN - 1);

    float xi0 = g_Xc[nlin*3+0], xi1 = g_Xc[nlin*3+1], xi2 = g_Xc[nlin*3+2];
    const int* Cb = C + b*NN;
    for (int j = lane; j < NN; j += 32) {
        float dx = __fadd_rn(xi0, -g_Xc[(size_t)(b*NN + j)*3 + 0]);
        float dy = __fadd_rn(xi1, -g_Xc[(size_t)(b*NN + j)*3 + 1]);
        float dz = __fadd_rn(xi2, -g_Xc[(size_t)(b*NN + j)*3 + 2]);
        float d2 = __fadd_rn(__fadd_rn(__fmul_rn(dx,dx), __fmul_rn(dy,dy)), __fmul_rn(dz,dz));
        if (Cb[j] <= 0) d2 = __fadd_rn(d2, BIGF);
        if (j == n)     d2 = __fadd_rn(d2, BIGF);
        s_d2[wid][j] = d2;
    }
    __syncwarp();

    float mi = g_maski[nlin];
    float cnt = 0.0f;
    for (int kk = 0; kk < KNB; kk++) {
        float bv = FLTMAX; int bi = 0x7fffffff;
        #pragma unroll 4
        for (int j = lane; j < NN; j += 32) {
            float v = s_d2[wid][j];
            if (v < bv || (v == bv && j < bi)) { bv = v; bi = j; }
        }
        #pragma unroll
        for (int off = 16; off > 0; off >>= 1) {
            float v2 = __shfl_down_sync(0xffffffffu, bv, off);
            int   i2 = __shfl_down_sync(0xffffffffu, bi, off);
            if (v2 < bv || (v2 == bv && i2 < bi)) { bv = v2; bi = i2; }
        }
        bi = __shfl_sync(0xffffffffu, bi, 0);
        if (lane == 0) {
            int e = nlin*KNB + kk;
            g_eidx[e] = bi;
            float mj = (Cb[bi] > 0) ? 1.0f : 0.0f;
            float mij = mi * mj;
            g_maskij[e] = mij;
            cnt += mij;
            s_d2[wid][bi] = FLTMAX;
        }
        __syncwarp();
    }
    if (lane == 0) { g_cnt[nlin] = cnt; g_denom[nlin] = cnt + EPSF; }
}

// ---------------- 3) edge features + edge_h init ----------------
__global__ void edge_feat_kernel(const float* __restrict__ We, const float* __restrict__ be)
{
    __shared__ float s_feat[KNB][EFI];
    int nlin = blockIdx.x;
    int b = nlin >> 11;
    int tid = threadIdx.x;

    if (tid < KNB) {
        int e = nlin*KNB + tid;
        int j = g_eidx[e];
        int jl = b*NN + j;
        float dv[3];
        #pragma unroll
        for (int d = 0; d < 3; d++) dv[d] = g_Xc[jl*3+d] - g_Xc[nlin*3+d];
        float dist = sqrtf(dv[0]*dv[0] + dv[1]*dv[1] + dv[2]*dv[2]);
        float Ri[9], Rj[9];
        #pragma unroll
        for (int q = 0; q < 9; q++) { Ri[q] = g_R[nlin*9+q]; Rj[q] = g_R[jl*9+q]; }
        float inv = 1.0f / (dist + EPSF);
        #pragma unroll
        for (int c = 0; c < 3; c++) {
            float loc = Ri[0*3+c]*dv[0] + Ri[1*3+c]*dv[1] + Ri[2*3+c]*dv[2];
            s_feat[tid][16 + c] = loc * inv;
        }
        #pragma unroll
        for (int ee = 0; ee < 3; ee++)
            #pragma unroll
            for (int ff = 0; ff < 3; ff++) {
                float r = Ri[0*3+ee]*Rj[0*3+ff] + Ri[1*3+ee]*Rj[1*3+ff] + Ri[2*3+ee]*Rj[2*3+ff];
                s_feat[tid][19 + ee*3 + ff] = r;
            }
        #pragma unroll
        for (int mc = 0; mc < 16; mc++) {
            float cm = (float)(20.0 * mc / 15.0);
            float z = (dist - cm) * 0.8f;
            s_feat[tid][mc] = expf(-z*z);
        }
    }
    __syncthreads();

    for (int idx = tid; idx < KNB*DE; idx += blockDim.x) {
        int k = idx >> 7;
        int c = idx & 127;
        int e = nlin*KNB + k;
        float acc = be[c];
        #pragma unroll
        for (int f = 0; f < EFI; f++) acc += s_feat[k][f] * We[f*DE + c];
        g_edgeh[(size_t)e*DE + c] = acc * g_maskij[e];
    }
}

// ---------------- 4) tf32 tensor-core GEMM (BM=128, BN=128, BK=16) ----------------
// MODE 0: out[z-slab] = A @ W[z-slab]                       (raw; node precompute)
// MODE 1: out = softplus(A@W + bias + Yi[i] + Zj[j])        (edge stage-1)
// MODE 2: edge_h = (edge_h + A@W + bias) * maskij           (edge update)
// MODE 3: node_h = (node_h + (A@W + cnt*bias)/denom)*mask_i (node update)
template<int KD, int NF, int MODE>
__global__ __launch_bounds__(256, 1) void mm_tc(
    const float* __restrict__ A, const float* __restrict__ W,
    const float* __restrict__ bias,
    const float* __restrict__ Yi, const float* __restrict__ Zj,
    float* __restrict__ out)
{
    constexpr int CH = KD / 16;             // 16-wide k-chunks
    __shared__ unsigned As[2][128][20];     // [row][k], stride 20 (pad)
    __shared__ unsigned Bs[2][16][136];     // [k][n],   stride 136 (pad)

    const int tid  = threadIdx.x;
    const int lane = tid & 31;
    const int wid  = tid >> 5;
    const int wm   = wid & 1;               // 2 warp rows (64 each)
    const int wn   = wid >> 1;              // 4 warp cols (32 each)

    const int rowBase = blockIdx.x * 128;
    const int n0 = blockIdx.y * 128;

    const float* Wp = W;
    float* outp = out;
    if (MODE == 0) {                        // slab select (Yi vs Zj weights)
        Wp   = W   + (size_t)blockIdx.z * KD * NF;
        outp = out + (size_t)blockIdx.z * NNODE * NF;
    }

    // global->smem loader indices
    const int laR = tid >> 2, laK = (tid & 3) * 4;        // A: 2 rows (laR, laR+64)
    const int lbK = tid >> 5, lbN = (tid & 31) * 4;       // B: 2 k-rows (lbK, lbK+8)
    const float* Ag0 = A  + (size_t)(rowBase + laR)      * KD + laK;
    const float* Ag1 = A  + (size_t)(rowBase + laR + 64) * KD + laK;
    const float* Wg0 = Wp + (size_t)lbK       * NF + n0 + lbN;
    const float* Wg1 = Wp + (size_t)(lbK + 8) * NF + n0 + lbN;

    float acc[4][4][4];
    #pragma unroll
    for (int i = 0; i < 4; i++)
        #pragma unroll
        for (int j = 0; j < 4; j++)
            #pragma unroll
            for (int q = 0; q < 4; q++) acc[i][j][q] = 0.0f;

    // preload chunk 0
    {
        float4 a0 = *(const float4*)Ag0;
        float4 a1 = *(const float4*)Ag1;
        float4 b0 = *(const float4*)Wg0;
        float4 b1 = *(const float4*)Wg1;
        *(uint4*)&As[0][laR   ][laK] = make_uint4(f2tf(a0.x), f2tf(a0.y), f2tf(a0.z), f2tf(a0.w));
        *(uint4*)&As[0][laR+64][laK] = make_uint4(f2tf(a1.x), f2tf(a1.y), f2tf(a1.z), f2tf(a1.w));
        *(uint4*)&Bs[0][lbK  ][lbN]  = make_uint4(f2tf(b0.x), f2tf(b0.y), f2tf(b0.z), f2tf(b0.w));
        *(uint4*)&Bs[0][lbK+8][lbN]  = make_uint4(f2tf(b1.x), f2tf(b1.y), f2tf(b1.z), f2tf(b1.w));
    }
    __syncthreads();

    int buf = 0;
    #pragma unroll 1
    for (int c = 0; c < CH; c++) {
        float4 pa0, pa1, pb0, pb1;
        if (c + 1 < CH) {
            pa0 = *(const float4*)(Ag0 + (c+1)*16);
            pa1 = *(const float4*)(Ag1 + (c+1)*16);
            pb0 = *(const float4*)(Wg0 + (size_t)(c+1)*16*NF);
            pb1 = *(const float4*)(Wg1 + (size_t)(c+1)*16*NF);
        }
        #pragma unroll
        for (int kk = 0; kk < 2; kk++) {
            const int kb = kk * 8;
            unsigned a[4][4], bq[4][2];
            #pragma unroll
            for (int mt = 0; mt < 4; mt++) {
                int r0 = wm*64 + mt*16 + (lane >> 2);
                a[mt][0] = As[buf][r0  ][kb + (lane & 3)];
                a[mt][1] = As[buf][r0+8][kb + (lane & 3)];
                a[mt][2] = As[buf][r0  ][kb + (lane & 3) + 4];
                a[mt][3] = As[buf][r0+8][kb + (lane & 3) + 4];
            }
            #pragma unroll
            for (int nt = 0; nt < 4; nt++) {
                int cc = wn*32 + nt*8 + (lane >> 2);
                bq[nt][0] = Bs[buf][kb + (lane & 3)    ][cc];
                bq[nt][1] = Bs[buf][kb + (lane & 3) + 4][cc];
            }
            #pragma unroll
            for (int mt = 0; mt < 4; mt++)
                #pragma unroll
                for (int nt = 0; nt < 4; nt++)
                    mma8(acc[mt][nt], a[mt], bq[nt]);
        }
        if (c + 1 < CH) {
            *(uint4*)&As[buf^1][laR   ][laK] = make_uint4(f2tf(pa0.x), f2tf(pa0.y), f2tf(pa0.z), f2tf(pa0.w));
            *(uint4*)&As[buf^1][laR+64][laK] = make_uint4(f2tf(pa1.x), f2tf(pa1.y), f2tf(pa1.z), f2tf(pa1.w));
            *(uint4*)&Bs[buf^1][lbK  ][lbN]  = make_uint4(f2tf(pb0.x), f2tf(pb0.y), f2tf(pb0.z), f2tf(pb0.w));
            *(uint4*)&Bs[buf^1][lbK+8][lbN]  = make_uint4(f2tf(pb1.x), f2tf(pb1.y), f2tf(pb1.z), f2tf(pb1.w));
        }
        __syncthreads();
        buf ^= 1;
    }

    // ---------------- epilogue ----------------
    #pragma unroll
    for (int mt = 0; mt < 4; mt++) {
        #pragma unroll
        for (int h = 0; h < 2; h++) {
            const int r = wm*64 + mt*16 + (lane >> 2) + h*8;
            const int grow = rowBase + r;

            const float* yip = nullptr; const float* zjp = nullptr;
            float mij = 0.f, dn = 1.f, mi = 0.f, cn = 0.f;
            const float* nhp = nullptr; const float* ehp = nullptr;
            if (MODE == 1) {
                int nlin = grow / KNB;
                int b = nlin >> 11;
                yip = Yi + (size_t)nlin * NF + n0;
                zjp = Zj + (size_t)(b*NN + g_eidx[grow]) * NF + n0;
            } else if (MODE == 2) {
                mij = g_maskij[grow];
                ehp = g_edgeh + (size_t)grow * DE + n0;
            } else if (MODE == 3) {
                dn = g_denom[grow]; mi = g_maski[grow]; cn = g_cnt[grow];
                nhp = g_nodeh + (size_t)grow * DN + n0;
            }

            float* op = outp + (size_t)grow * NF + n0;
            #pragma unroll
            for (int nt = 0; nt < 4; nt++) {
                const int c0 = wn*32 + nt*8 + 2*(lane & 3);
                float v0 = acc[mt][nt][h*2 + 0];
                float v1 = acc[mt][nt][h*2 + 1];
                if (MODE == 0) {
                    *(float2*)(op + c0) = make_float2(v0, v1);
                } else if (MODE == 1) {
                    float2 bsv = *(const float2*)(bias + n0 + c0);
                    float2 yv  = *(const float2*)(yip + c0);
                    float2 zv  = *(const float2*)(zjp + c0);
                    v0 = softplus_f(v0 + bsv.x + yv.x + zv.x);
                    v1 = softplus_f(v1 + bsv.y + yv.y + zv.y);
                    *(float2*)(op + c0) = make_float2(v0, v1);
                } else if (MODE == 2) {
                    float2 bsv = *(const float2*)(bias + n0 + c0);
                    float2 ev  = *(const float2*)(ehp + c0);
                    v0 = (ev.x + v0 + bsv.x) * mij;
                    v1 = (ev.y + v1 + bsv.y) * mij;
                    *(float2*)(op + c0) = make_float2(v0, v1);
                } else {
                    float2 bsv = *(const float2*)(bias + n0 + c0);
                    float2 nv  = *(const float2*)(nhp + c0);
                    v0 = (nv.x + (v0 + cn*bsv.x) / dn) * mi;
                    v1 = (nv.y + (v1 + cn*bsv.y) / dn) * mi;
                    *(float2*)(op + c0) = make_float2(v0, v1);
                }
            }
        }
    }
}

// ---------------- 5) masked k-sum of t1 per node ----------------
__global__ void ksum_kernel()
{
    __shared__ float sm[KNB];
    int nlin = blockIdx.x;
    int c = threadIdx.x;
    if (c < KNB) sm[c] = g_maskij[nlin*KNB + c];
    __syncthreads();
    float s = 0.0f;
    #pragma unroll
    for (int k = 0; k < KNB; k++)
        s += sm[k] * g_t1[(size_t)(nlin*KNB + k)*DN + c];
    g_ksum[(size_t)nlin*DN + c] = s;
}

// ---------------- 6) pack outputs ----------------
__global__ void copy_out_kernel(float* __restrict__ out)
{
    const int S0 = NNODE*DN;
    const int S1 = ETOT*DE;
    const int S2 = ETOT;
    const int S3 = NNODE;
    const int TOT = S0 + S1 + S2 + S3 + ETOT;
    for (int i = blockIdx.x*blockDim.x + threadIdx.x; i < TOT; i += gridDim.x*blockDim.x) {
        float v;
        if (i < S0)                    v = g_nodeh[i];
        else if (i < S0+S1)            v = g_edgeh[i - S0];
        else if (i < S0+S1+S2)         v = (float)g_eidx[i - S0 - S1];
        else if (i < S0+S1+S2+S3)      v = g_maski[i - S0 - S1 - S2];
        else                           v = g_maskij[i - S0 - S1 - S2 - S3];
        out[i] = v;
    }
}

// ---------------- launch ----------------
extern "C" void kernel_launch(void* const* d_in, const int* in_sizes, int n_in,
                              void* d_out, int out_size)
{
    const float* X    = (const float*)d_in[0];
    const int*   C    = (const int*)  d_in[1];
    const float* Wn   = (const float*)d_in[2];
    const float* bn   = (const float*)d_in[3];
    const float* We   = (const float*)d_in[4];
    const float* be   = (const float*)d_in[5];
    const float* Wm1  = (const float*)d_in[6];
    const float* bm1  = (const float*)d_in[7];
    const float* Wm2  = (const float*)d_in[8];
    const float* bm2  = (const float*)d_in[9];
    const float* Wue1 = (const float*)d_in[10];
    const float* bue1 = (const float*)d_in[11];
    const float* Wue2 = (const float*)d_in[12];
    const float* bue2 = (const float*)d_in[13];

    frame_kernel<<<NNODE/8, 256>>>(X, C, Wn, bn);
    knn_kernel<<<NNODE/4, 128>>>(C);
    edge_feat_kernel<<<NNODE, 128>>>(We, be);

    float* Ym; cudaGetSymbolAddress((void**)&Ym, g_Ym);
    float* Ye; cudaGetSymbolAddress((void**)&Ye, g_Ye);
    float* T1; cudaGetSymbolAddress((void**)&T1, g_t1);
    float* T2; cudaGetSymbolAddress((void**)&T2, g_t2);
    float* Eh; cudaGetSymbolAddress((void**)&Eh, g_edgeh);
    float* Nh; cudaGetSymbolAddress((void**)&Nh, g_nodeh);
    float* Ks; cudaGetSymbolAddress((void**)&Ks, g_ksum);

    const int MD = 2*DN + DE;  // 640
    for (int l = 0; l < NL; l++) {
        const float* Wm1l  = Wm1  + (size_t)l*MD*DN;
        const float* Wue1l = Wue1 + (size_t)l*MD*DE;
        // node-side precompute: Yi/Zj for m-path and e-path (slab via blockIdx.z)
        mm_tc<256, 256, 0><<<dim3(NNODE/128, 2, 2), 256>>>(Nh, Wm1l,  nullptr, nullptr, nullptr, Ym);
        mm_tc<256, 128, 0><<<dim3(NNODE/128, 1, 2), 256>>>(Nh, Wue1l, nullptr, nullptr, nullptr, Ye);
        // edge stage-1 GEMMs (K=128, e-part of W), fused gather-add + softplus
        mm_tc<128, 256, 1><<<dim3(ETOT/128, 2), 256>>>(
            Eh, Wm1l  + (size_t)2*DN*DN, bm1  + l*DN, Ym, Ym + (size_t)NNODE*DN, T1);
        mm_tc<128, 128, 1><<<dim3(ETOT/128, 1), 256>>>(
            Eh, Wue1l + (size_t)2*DN*DE, bue1 + l*DE, Ye, Ye + (size_t)NNODE*DE, T2);
        // node update: masked k-sum then GEMM with fused residual update
        ksum_kernel<<<NNODE, DN>>>();
        mm_tc<256, 256, 3><<<dim3(NNODE/128, 2), 256>>>(
            Ks, Wm2 + (size_t)l*DN*DN, bm2 + l*DN, nullptr, nullptr, Nh);
        // edge update (in-place on edge_h)
        mm_tc<128, 128, 2><<<dim3(ETOT/128, 1), 256>>>(
            T2, Wue2 + (size_t)l*DE*DE, bue2 + l*DE, nullptr, nullptr, Eh);
    }

    copy_out_kernel<<<16384, 256>>>((float*)d_out);
}

// round 4
// speedup vs baseline: 5.1545x; 1.3658x over previous
#include <cuda_runtime.h>
#include <math.h>

// ---------------- problem constants ----------------
#define BB   2
#define NN   2048
#define KNB  30
#define DN   256
#define DE   128
#define NL   3
#define NFI  12
#define EFI  28
#define ETOT (BB*NN*KNB)  // 122880
#define NNODE (BB*NN)     // 4096
#define EPSF 1e-6f
#define BIGF 1e9f
#define FLTMAX 3.402823466e38f

// ---------------- scratch ----------------
__device__ float g_nodeh[NNODE*DN];
__device__ float g_edgeh[ETOT*DE];
__device__ int   g_eidx [ETOT];
__device__ float g_maski[NNODE];
__device__ float g_maskij[ETOT];
__device__ float g_denom[NNODE];
__device__ float g_cnt  [NNODE];
__device__ float g_R  [NNODE*9];
__device__ float g_Xc [NNODE*3];
__device__ float g_t1 [ETOT*DN];
__device__ float g_t2 [ETOT*DE];
__device__ float g_Ym [2*NNODE*DN];
__device__ float g_Ye [2*NNODE*DE];
__device__ float g_ksum[NNODE*DN];

__device__ __forceinline__ float softplus_f(float x) {
    return fmaxf(x, 0.0f) + log1pf(expf(-fabsf(x)));
}
__device__ __forceinline__ unsigned f2tf(float x) {
    unsigned r; asm("cvt.rna.tf32.f32 %0, %1;" : "=r"(r) : "f"(x)); return r;
}
__device__ __forceinline__ void mma8(float* c, const unsigned* a, const unsigned* b) {
    asm volatile(
        "mma.sync.aligned.m16n8k8.row.col.f32.tf32.tf32.f32 "
        "{%0,%1,%2,%3},{%4,%5,%6,%7},{%8,%9},{%0,%1,%2,%3};"
        : "+f"(c[0]), "+f"(c[1]), "+f"(c[2]), "+f"(c[3])
        : "r"(a[0]), "r"(a[1]), "r"(a[2]), "r"(a[3]), "r"(b[0]), "r"(b[1]));
}
__device__ __forceinline__ void cp16(unsigned dst, const float* src) {
    asm volatile("cp.async.cg.shared.global [%0], [%1], 16;" :: "r"(dst), "l"(src));
}
#define CP_COMMIT() asm volatile("cp.async.commit_group;")
#define CP_WAIT2()  asm volatile("cp.async.wait_group 2;")

// ---------------- 1) per-node frame, features, node_h init ----------------
__global__ void frame_kernel(const float* __restrict__ X, const int* __restrict__ C,
                             const float* __restrict__ Wn, const float* __restrict__ bn)
{
    __shared__ float s_feat[8][12];
    __shared__ float s_mask[8];
    int warp = threadIdx.x >> 5;
    int lane = threadIdx.x & 31;
    int nlin = blockIdx.x * 8 + warp;

    if (lane == 0) {
        const float* xr = X + (size_t)nlin * 12;
        float Na[3], CA[3], Ct[3], Oa[3];
        #pragma unroll
        for (int d = 0; d < 3; d++) { Na[d]=xr[d]; CA[d]=xr[3+d]; Ct[d]=xr[6+d]; Oa[d]=xr[9+d]; }
        #pragma unroll
        for (int d = 0; d < 3; d++) {
            float s = __fadd_rn(__fadd_rn(__fadd_rn(Na[d], CA[d]), Ct[d]), Oa[d]);
            g_Xc[nlin*3 + d] = __fmul_rn(s, 0.25f);
        }
        float b1[3], b2[3], b3[3], v0[3];
        #pragma unroll
        for (int d = 0; d < 3; d++) {
            b1[d] = CA[d] - Na[d];
            b2[d] = Ct[d] - CA[d];
            b3[d] = Oa[d] - Ct[d];
            v0[d] = Na[d] - CA[d];
        }
        float nb2 = sqrtf(b2[0]*b2[0] + b2[1]*b2[1] + b2[2]*b2[2]);
        float u[3];
        #pragma unroll
        for (int d = 0; d < 3; d++) u[d] = b2[d] / (nb2 + EPSF);
        float dotv = v0[0]*u[0] + v0[1]*u[1] + v0[2]*u[2];
        float t[3];
        #pragma unroll
        for (int d = 0; d < 3; d++) t[d] = v0[d] - dotv * u[d];
        float nt = sqrtf(t[0]*t[0] + t[1]*t[1] + t[2]*t[2]);
        float v[3];
        #pragma unroll
        for (int d = 0; d < 3; d++) v[d] = t[d] / (nt + EPSF);
        float w[3];
        w[0] = u[1]*v[2] - u[2]*v[1];
        w[1] = u[2]*v[0] - u[0]*v[2];
        w[2] = u[0]*v[1] - u[1]*v[0];
        #pragma unroll
        for (int d = 0; d < 3; d++) {
            g_R[nlin*9 + d*3 + 0] = u[d];
            g_R[nlin*9 + d*3 + 1] = v[d];
            g_R[nlin*9 + d*3 + 2] = w[d];
        }
        float nb1 = sqrtf(b1[0]*b1[0] + b1[1]*b1[1] + b1[2]*b1[2]);
        float nb3 = sqrtf(b3[0]*b3[0] + b3[1]*b3[1] + b3[2]*b3[2]);
        #pragma unroll
        for (int d = 0; d < 3; d++) {
            s_feat[warp][0 + d] = b1[d] / (nb1 + EPSF);
            s_feat[warp][4 + d] = b2[d] / (nb2 + EPSF);
            s_feat[warp][8 + d] = b3[d] / (nb3 + EPSF);
        }
        s_feat[warp][3]  = logf(nb1 + EPSF);
        s_feat[warp][7]  = logf(nb2 + EPSF);
        s_feat[warp][11] = logf(nb3 + EPSF);
        float mk = (C[nlin] > 0) ? 1.0f : 0.0f;
        s_mask[warp] = mk;
        g_maski[nlin] = mk;
    }
    __syncwarp();

    float f[12];
    #pragma unroll
    for (int i = 0; i < 12; i++) f[i] = s_feat[warp][i];
    float mk = s_mask[warp];
    #pragma unroll
    for (int r = 0; r < 8; r++) {
        int c = lane + r * 32;
        float acc = bn[c];
        #pragma unroll
        for (int ff = 0; ff < NFI; ff++) acc += f[ff] * Wn[ff*DN + c];
        g_nodeh[(size_t)nlin*DN + c] = acc * mk;
    }
}

// ---------------- 2) kNN: warp-per-node, exact semantics ----------------
__global__ __launch_bounds__(128) void knn_kernel(const int* __restrict__ C)
{
    __shared__ float s_d2[4][NN];
    int wid = threadIdx.x >> 5;
    int lane = threadIdx.x & 31;
    int nlin = blockIdx.x * 4 + wid;
    int b = nlin >> 11;
    int n = nlin & (NN - 1);

    float xi0 = g_Xc[nlin*3+0], xi1 = g_Xc[nlin*3+1], xi2 = g_Xc[nlin*3+2];
    const int* Cb = C + b*NN;
    for (int j = lane; j < NN; j += 32) {
        float dx = __fadd_rn(xi0, -g_Xc[(size_t)(b*NN + j)*3 + 0]);
        float dy = __fadd_rn(xi1, -g_Xc[(size_t)(b*NN + j)*3 + 1]);
        float dz = __fadd_rn(xi2, -g_Xc[(size_t)(b*NN + j)*3 + 2]);
        float d2 = __fadd_rn(__fadd_rn(__fmul_rn(dx,dx), __fmul_rn(dy,dy)), __fmul_rn(dz,dz));
        if (Cb[j] <= 0) d2 = __fadd_rn(d2, BIGF);
        if (j == n)     d2 = __fadd_rn(d2, BIGF);
        s_d2[wid][j] = d2;
    }
    __syncwarp();

    float mi = g_maski[nlin];
    float cnt = 0.0f;
    for (int kk = 0; kk < KNB; kk++) {
        float bv = FLTMAX; int bi = 0x7fffffff;
        #pragma unroll 4
        for (int j = lane; j < NN; j += 32) {
            float v = s_d2[wid][j];
            if (v < bv || (v == bv && j < bi)) { bv = v; bi = j; }
        }
        #pragma unroll
        for (int off = 16; off > 0; off >>= 1) {
            float v2 = __shfl_down_sync(0xffffffffu, bv, off);
            int   i2 = __shfl_down_sync(0xffffffffu, bi, off);
            if (v2 < bv || (v2 == bv && i2 < bi)) { bv = v2; bi = i2; }
        }
        bi = __shfl_sync(0xffffffffu, bi, 0);
        if (lane == 0) {
            int e = nlin*KNB + kk;
            g_eidx[e] = bi;
            float mj = (Cb[bi] > 0) ? 1.0f : 0.0f;
            float mij = mi * mj;
            g_maskij[e] = mij;
            cnt += mij;
            s_d2[wid][bi] = FLTMAX;
        }
        __syncwarp();
    }
    if (lane == 0) { g_cnt[nlin] = cnt; g_denom[nlin] = cnt + EPSF; }
}

// ---------------- 3) edge features + edge_h init ----------------
__global__ void edge_feat_kernel(const float* __restrict__ We, const float* __restrict__ be)
{
    __shared__ float s_feat[KNB][EFI];
    int nlin = blockIdx.x;
    int b = nlin >> 11;
    int tid = threadIdx.x;

    if (tid < KNB) {
        int e = nlin*KNB + tid;
        int j = g_eidx[e];
        int jl = b*NN + j;
        float dv[3];
        #pragma unroll
        for (int d = 0; d < 3; d++) dv[d] = g_Xc[jl*3+d] - g_Xc[nlin*3+d];
        float dist = sqrtf(dv[0]*dv[0] + dv[1]*dv[1] + dv[2]*dv[2]);
        float Ri[9], Rj[9];
        #pragma unroll
        for (int q = 0; q < 9; q++) { Ri[q] = g_R[nlin*9+q]; Rj[q] = g_R[jl*9+q]; }
        float inv = 1.0f / (dist + EPSF);
        #pragma unroll
        for (int c = 0; c < 3; c++) {
            float loc = Ri[0*3+c]*dv[0] + Ri[1*3+c]*dv[1] + Ri[2*3+c]*dv[2];
            s_feat[tid][16 + c] = loc * inv;
        }
        #pragma unroll
        for (int ee = 0; ee < 3; ee++)
            #pragma unroll
            for (int ff = 0; ff < 3; ff++) {
                float r = Ri[0*3+ee]*Rj[0*3+ff] + Ri[1*3+ee]*Rj[1*3+ff] + Ri[2*3+ee]*Rj[2*3+ff];
                s_feat[tid][19 + ee*3 + ff] = r;
            }
        #pragma unroll
        for (int mc = 0; mc < 16; mc++) {
            float cm = (float)(20.0 * mc / 15.0);
            float z = (dist - cm) * 0.8f;
            s_feat[tid][mc] = expf(-z*z);
        }
    }
    __syncthreads();

    for (int idx = tid; idx < KNB*DE; idx += blockDim.x) {
        int k = idx >> 7;
        int c = idx & 127;
        int e = nlin*KNB + k;
        float acc = be[c];
        #pragma unroll
        for (int f = 0; f < EFI; f++) acc += s_feat[k][f] * We[f*DE + c];
        g_edgeh[(size_t)e*DE + c] = acc * g_maskij[e];
    }
}

// ---------------- 4) tf32 TC GEMM, 4-stage cp.async pipeline ----------------
// BM=128, BN=128, BK=16, dynamic smem. fp32 in smem; cvt.rna at fragment load.
// MODE 0: out[z-slab] = A @ W[z-slab]
// MODE 1: out = softplus(A@W + bias + Yi[i] + Zj[j])
// MODE 2: edge_h = (edge_h + A@W + bias) * maskij
// MODE 3: node_h = (node_h + (A@W + cnt*bias)/denom)*mask_i
#define MM_ST 4
#define MM_AS (128*20)              // floats per A stage (pad 16->20)
#define MM_BS (16*132)              // floats per B stage (pad 128->132)
#define MM_SMEM ((MM_ST*(MM_AS+MM_BS))*4)

template<int KD, int NF, int MODE>
__global__ __launch_bounds__(256, 2) void mm_tc(
    const float* __restrict__ A, const float* __restrict__ W,
    const float* __restrict__ bias,
    const float* __restrict__ Yi, const float* __restrict__ Zj,
    float* __restrict__ out)
{
    constexpr int CH = KD / 16;
    extern __shared__ float smem_dyn[];
    float* Asm = smem_dyn;                 // [ST][128][20]
    float* Bsm = smem_dyn + MM_ST*MM_AS;   // [ST][16][132]

    const int tid  = threadIdx.x;
    const int lane = tid & 31;
    const int wid  = tid >> 5;
    const int wm   = wid & 1;
    const int wn   = wid >> 1;

    const int rowBase = blockIdx.x * 128;
    const int n0 = blockIdx.y * 128;

    const float* Wp = W;
    float* outp = out;
    if (MODE == 0) {
        Wp   = W   + (size_t)blockIdx.z * KD * NF;
        outp = out + (size_t)blockIdx.z * NNODE * NF;
    }

    // loader: A — each thread 2x16B of one row; B — each thread 2x16B of one k-row
    const int laR = tid >> 1, laK = (tid & 1) * 8;
    const int lbK = tid >> 4, lbN = (tid & 15) * 8;
    const float* Ag = A  + (size_t)(rowBase + laR) * KD + laK;
    const float* Wg = Wp + (size_t)lbK * NF + n0 + lbN;

    const unsigned sa = (unsigned)__cvta_generic_to_shared(Asm) + (laR*20 + laK)*4;
    const unsigned sb = (unsigned)__cvta_generic_to_shared(Bsm) + (lbK*132 + lbN)*4;

    // prologue: fill ST-1 stages
    #pragma unroll
    for (int s = 0; s < MM_ST-1; s++) {
        cp16(sa + s*MM_AS*4,      Ag + s*16);
        cp16(sa + s*MM_AS*4 + 16, Ag + s*16 + 4);
        cp16(sb + s*MM_BS*4,      Wg + (size_t)s*16*NF);
        cp16(sb + s*MM_BS*4 + 16, Wg + (size_t)s*16*NF + 4);
        CP_COMMIT();
    }

    float acc[4][4][4];
    #pragma unroll
    for (int i = 0; i < 4; i++)
        #pragma unroll
        for (int j = 0; j < 4; j++)
            #pragma unroll
            for (int q = 0; q < 4; q++) acc[i][j][q] = 0.0f;

    #pragma unroll 1
    for (int c = 0; c < CH; c++) {
        CP_WAIT2();
        __syncthreads();

        // issue chunk c+ST-1 into slot (c+ST-1)%ST (safe: that slot's compute done)
        if (c + MM_ST-1 < CH) {
            const int slot = (c + MM_ST-1) & (MM_ST-1);
            const int cc = c + MM_ST-1;
            cp16(sa + slot*MM_AS*4,      Ag + cc*16);
            cp16(sa + slot*MM_AS*4 + 16, Ag + cc*16 + 4);
            cp16(sb + slot*MM_BS*4,      Wg + (size_t)cc*16*NF);
            cp16(sb + slot*MM_BS*4 + 16, Wg + (size_t)cc*16*NF + 4);
        }
        CP_COMMIT();

        const float* As = Asm + (c & (MM_ST-1)) * MM_AS;
        const float* Bs = Bsm + (c & (MM_ST-1)) * MM_BS;

        #pragma unroll
        for (int kk = 0; kk < 2; kk++) {
            const int kb = kk * 8;
            unsigned a[4][4], bq[4][2];
            #pragma unroll
            for (int mt = 0; mt < 4; mt++) {
                int r0 = wm*64 + mt*16 + (lane >> 2);
                a[mt][0] = f2tf(As[(r0  )*20 + kb + (lane & 3)]);
                a[mt][1] = f2tf(As[(r0+8)*20 + kb + (lane & 3)]);
                a[mt][2] = f2tf(As[(r0  )*20 + kb + (lane & 3) + 4]);
                a[mt][3] = f2tf(As[(r0+8)*20 + kb + (lane & 3) + 4]);
            }
            #pragma unroll
            for (int nt = 0; nt < 4; nt++) {
                int cc2 = wn*32 + nt*8 + (lane >> 2);
                bq[nt][0] = f2tf(Bs[(kb + (lane & 3)    )*132 + cc2]);
                bq[nt][1] = f2tf(Bs[(kb + (lane & 3) + 4)*132 + cc2]);
            }
            #pragma unroll
            for (int mt = 0; mt < 4; mt++)
                #pragma unroll
                for (int nt = 0; nt < 4; nt++)
                    mma8(acc[mt][nt], a[mt], bq[nt]);
        }
        __syncthreads();
    }

    // ---------------- epilogue ----------------
    #pragma unroll
    for (int mt = 0; mt < 4; mt++) {
        #pragma unroll
        for (int h = 0; h < 2; h++) {
            const int r = wm*64 + mt*16 + (lane >> 2) + h*8;
            const int grow = rowBase + r;

            const float* yip = nullptr; const float* zjp = nullptr;
            float mij = 0.f, dn = 1.f, mi = 0.f, cn = 0.f;
            const float* nhp = nullptr; const float* ehp = nullptr;
            if (MODE == 1) {
                int nlin = grow / KNB;
                int b = nlin >> 11;
                yip = Yi + (size_t)nlin * NF + n0;
                zjp = Zj + (size_t)(b*NN + g_eidx[grow]) * NF + n0;
            } else if (MODE == 2) {
                mij = g_maskij[grow];
                ehp = g_edgeh + (size_t)grow * DE + n0;
            } else if (MODE == 3) {
                dn = g_denom[grow]; mi = g_maski[grow]; cn = g_cnt[grow];
                nhp = g_nodeh + (size_t)grow * DN + n0;
            }

            float* op = outp + (size_t)grow * NF + n0;
            #pragma unroll
            for (int nt = 0; nt < 4; nt++) {
                const int c0 = wn*32 + nt*8 + 2*(lane & 3);
                float v0 = acc[mt][nt][h*2 + 0];
                float v1 = acc[mt][nt][h*2 + 1];
                if (MODE == 0) {
                    *(float2*)(op + c0) = make_float2(v0, v1);
                } else if (MODE == 1) {
                    float2 bsv = *(const float2*)(bias + n0 + c0);
                    float2 yv  = *(const float2*)(yip + c0);
                    float2 zv  = *(const float2*)(zjp + c0);
                    v0 = softplus_f(v0 + bsv.x + yv.x + zv.x);
                    v1 = softplus_f(v1 + bsv.y + yv.y + zv.y);
                    *(float2*)(op + c0) = make_float2(v0, v1);
                } else if (MODE == 2) {
                    float2 bsv = *(const float2*)(bias + n0 + c0);
                    float2 ev  = *(const float2*)(ehp + c0);
                    v0 = (ev.x + v0 + bsv.x) * mij;
                    v1 = (ev.y + v1 + bsv.y) * mij;
                    *(float2*)(op + c0) = make_float2(v0, v1);
                } else {
                    float2 bsv = *(const float2*)(bias + n0 + c0);
                    float2 nv  = *(const float2*)(nhp + c0);
                    v0 = (nv.x + (v0 + cn*bsv.x) / dn) * mi;
                    v1 = (nv.y + (v1 + cn*bsv.y) / dn) * mi;
                    *(float2*)(op + c0) = make_float2(v0, v1);
                }
            }
        }
    }
}

// ---------------- 5) masked k-sum of t1 per node ----------------
__global__ void ksum_kernel()
{
    __shared__ float sm[KNB];
    int nlin = blockIdx.x;
    int c = threadIdx.x;
    if (c < KNB) sm[c] = g_maskij[nlin*KNB + c];
    __syncthreads();
    float s = 0.0f;
    #pragma unroll
    for (int k = 0; k < KNB; k++)
        s += sm[k] * g_t1[(size_t)(nlin*KNB + k)*DN + c];
    g_ksum[(size_t)nlin*DN + c] = s;
}

// ---------------- 6) pack outputs (float4) ----------------
__global__ void copy_out_kernel(float4* __restrict__ out)
{
    const int S0 = NNODE*DN/4;
    const int S1 = ETOT*DE/4;
    const int S2 = ETOT/4;
    const int S3 = NNODE/4;
    const int TOT = S0 + S1 + S2 + S3 + ETOT/4;
    const float4* nh = (const float4*)g_nodeh;
    const float4* eh = (const float4*)g_edgeh;
    const int4*   ei = (const int4*)g_eidx;
    const float4* mi = (const float4*)g_maski;
    const float4* mj = (const float4*)g_maskij;
    for (int i = blockIdx.x*blockDim.x + threadIdx.x; i < TOT; i += gridDim.x*blockDim.x) {
        float4 v;
        if (i < S0)                    v = nh[i];
        else if (i < S0+S1)            v = eh[i - S0];
        else if (i < S0+S1+S2) {
            int4 t = ei[i - S0 - S1];
            v = make_float4((float)t.x, (float)t.y, (float)t.z, (float)t.w);
        }
        else if (i < S0+S1+S2+S3)      v = mi[i - S0 - S1 - S2];
        else                           v = mj[i - S0 - S1 - S2 - S3];
        out[i] = v;
    }
}

// ---------------- launch ----------------
extern "C" void kernel_launch(void* const* d_in, const int* in_sizes, int n_in,
                              void* d_out, int out_size)
{
    const float* X    = (const float*)d_in[0];
    const int*   C    = (const int*)  d_in[1];
    const float* Wn   = (const float*)d_in[2];
    const float* bn   = (const float*)d_in[3];
    const float* We   = (const float*)d_in[4];
    const float* be   = (const float*)d_in[5];
    const float* Wm1  = (const float*)d_in[6];
    const float* bm1  = (const float*)d_in[7];
    const float* Wm2  = (const float*)d_in[8];
    const float* bm2  = (const float*)d_in[9];
    const float* Wue1 = (const float*)d_in[10];
    const float* bue1 = (const float*)d_in[11];
    const float* Wue2 = (const float*)d_in[12];
    const float* bue2 = (const float*)d_in[13];

    // raise dynamic smem limit for all GEMM instantiations (idempotent, capture-safe)
    cudaFuncSetAttribute(mm_tc<256,256,0>, cudaFuncAttributeMaxDynamicSharedMemorySize, MM_SMEM);
    cudaFuncSetAttribute(mm_tc<256,128,0>, cudaFuncAttributeMaxDynamicSharedMemorySize, MM_SMEM);
    cudaFuncSetAttribute(mm_tc<128,256,1>, cudaFuncAttributeMaxDynamicSharedMemorySize, MM_SMEM);
    cudaFuncSetAttribute(mm_tc<128,128,1>, cudaFuncAttributeMaxDynamicSharedMemorySize, MM_SMEM);
    cudaFuncSetAttribute(mm_tc<256,256,3>, cudaFuncAttributeMaxDynamicSharedMemorySize, MM_SMEM);
    cudaFuncSetAttribute(mm_tc<128,128,2>, cudaFuncAttributeMaxDynamicSharedMemorySize, MM_SMEM);

    frame_kernel<<<NNODE/8, 256>>>(X, C, Wn, bn);
    knn_kernel<<<NNODE/4, 128>>>(C);
    edge_feat_kernel<<<NNODE, 128>>>(We, be);

    float* Ym; cudaGetSymbolAddress((void**)&Ym, g_Ym);
    float* Ye; cudaGetSymbolAddress((void**)&Ye, g_Ye);
    float* T1; cudaGetSymbolAddress((void**)&T1, g_t1);
    float* T2; cudaGetSymbolAddress((void**)&T2, g_t2);
    float* Eh; cudaGetSymbolAddress((void**)&Eh, g_edgeh);
    float* Nh; cudaGetSymbolAddress((void**)&Nh, g_nodeh);
    float* Ks; cudaGetSymbolAddress((void**)&Ks, g_ksum);

    const int MD = 2*DN + DE;  // 640
    for (int l = 0; l < NL; l++) {
        const float* Wm1l  = Wm1  + (size_t)l*MD*DN;
        const float* Wue1l = Wue1 + (size_t)l*MD*DE;
        mm_tc<256, 256, 0><<<dim3(NNODE/128, 2, 2), 256, MM_SMEM>>>(Nh, Wm1l,  nullptr, nullptr, nullptr, Ym);
        mm_tc<256, 128, 0><<<dim3(NNODE/128, 1, 2), 256, MM_SMEM>>>(Nh, Wue1l, nullptr, nullptr, nullptr, Ye);
        mm_tc<128, 256, 1><<<dim3(ETOT/128, 2), 256, MM_SMEM>>>(
            Eh, Wm1l  + (size_t)2*DN*DN, bm1  + l*DN, Ym, Ym + (size_t)NNODE*DN, T1);
        mm_tc<128, 128, 1><<<dim3(ETOT/128, 1), 256, MM_SMEM>>>(
            Eh, Wue1l + (size_t)2*DN*DE, bue1 + l*DE, Ye, Ye + (size_t)NNODE*DE, T2);
        ksum_kernel<<<NNODE, DN>>>();
        mm_tc<256, 256, 3><<<dim3(NNODE/128, 2), 256, MM_SMEM>>>(
            Ks, Wm2 + (size_t)l*DN*DN, bm2 + l*DN, nullptr, nullptr, Nh);
        mm_tc<128, 128, 2><<<dim3(ETOT/128, 1), 256, MM_SMEM>>>(
            T2, Wue2 + (size_t)l*DE*DE, bue2 + l*DE, nullptr, nullptr, Eh);
    }

    copy_out_kernel<<<2048, 256>>>((float4*)d_out);
}

// round 5
// speedup vs baseline: 5.2270x; 1.0141x over previous
#include <cuda_runtime.h>
#include <math.h>

// ---------------- problem constants ----------------
#define BB   2
#define NN   2048
#define KNB  30
#define DN   256
#define DE   128
#define NL   3
#define NFI  12
#define EFI  28
#define ETOT (BB*NN*KNB)  // 122880
#define NNODE (BB*NN)     // 4096
#define EPSF 1e-6f
#define BIGF 1e9f
#define FLTMAX 3.402823466e38f

// ---------------- scratch ----------------
__device__ float g_nodeh [NNODE*DN];
__device__ float g_nodehr[NNODE*DN];      // tf32-rounded shadow (MMA input)
__device__ float g_edgeh [ETOT*DE];
__device__ float g_edgehr[ETOT*DE];       // tf32-rounded shadow (MMA input)
__device__ int   g_eidx [ETOT];
__device__ float g_maski[NNODE];
__device__ float g_maskij[ETOT];
__device__ float g_denom[NNODE];
__device__ float g_cnt  [NNODE];
__device__ float g_R  [NNODE*9];
__device__ float g_Xc [NNODE*3];
__device__ float g_t1 [ETOT*DN];          // fp32 (scalar-consumed)
__device__ float g_t2 [ETOT*DE];          // tf32-rounded at write (MMA input)
__device__ float g_Ym [2*NNODE*DN];
__device__ float g_Ye [2*NNODE*DE];
__device__ float g_ksum[NNODE*DN];        // tf32-rounded at write (MMA input)
__device__ float g_Wr [3*(640*DN + 640*DE + DN*DN + DE*DE)]; // rounded weights

#define WR_M1   0
#define WR_UE1  (3*640*DN)
#define WR_M2   (WR_UE1 + 3*640*DE)
#define WR_UE2  (WR_M2 + 3*DN*DN)
#define WR_TOT  (WR_UE2 + 3*DE*DE)

__device__ __forceinline__ float softplus_f(float x) {
    return fmaxf(x, 0.0f) + log1pf(expf(-fabsf(x)));
}
__device__ __forceinline__ unsigned f2tf(float x) {
    unsigned r; asm("cvt.rna.tf32.f32 %0, %1;" : "=r"(r) : "f"(x)); return r;
}
__device__ __forceinline__ float rtf(float x) { return __uint_as_float(f2tf(x)); }
__device__ __forceinline__ void mma8(float* c, const unsigned* a, const unsigned* b) {
    asm volatile(
        "mma.sync.aligned.m16n8k8.row.col.f32.tf32.tf32.f32 "
        "{%0,%1,%2,%3},{%4,%5,%6,%7},{%8,%9},{%0,%1,%2,%3};"
        : "+f"(c[0]), "+f"(c[1]), "+f"(c[2]), "+f"(c[3])
        : "r"(a[0]), "r"(a[1]), "r"(a[2]), "r"(a[3]), "r"(b[0]), "r"(b[1]));
}
__device__ __forceinline__ void cp16(unsigned dst, const float* src) {
    asm volatile("cp.async.cg.shared.global [%0], [%1], 16;" :: "r"(dst), "l"(src));
}
#define CP_COMMIT() asm volatile("cp.async.commit_group;")
#define CP_WAIT2()  asm volatile("cp.async.wait_group 2;")

// ---------------- 0) round all weight tensors to tf32 ----------------
__global__ void round_w_kernel(const float* __restrict__ Wm1, const float* __restrict__ Wue1,
                               const float* __restrict__ Wm2, const float* __restrict__ Wue2)
{
    for (int i = blockIdx.x*blockDim.x + threadIdx.x; i < WR_TOT; i += gridDim.x*blockDim.x) {
        float v;
        if (i < WR_UE1)        v = Wm1 [i];
        else if (i < WR_M2)    v = Wue1[i - WR_UE1];
        else if (i < WR_UE2)   v = Wm2 [i - WR_M2];
        else                   v = Wue2[i - WR_UE2];
        g_Wr[i] = rtf(v);
    }
}

// ---------------- 1) per-node frame, features, node_h init ----------------
__global__ void frame_kernel(const float* __restrict__ X, const int* __restrict__ C,
                             const float* __restrict__ Wn, const float* __restrict__ bn)
{
    __shared__ float s_feat[8][12];
    __shared__ float s_mask[8];
    int warp = threadIdx.x >> 5;
    int lane = threadIdx.x & 31;
    int nlin = blockIdx.x * 8 + warp;

    if (lane == 0) {
        const float* xr = X + (size_t)nlin * 12;
        float Na[3], CA[3], Ct[3], Oa[3];
        #pragma unroll
        for (int d = 0; d < 3; d++) { Na[d]=xr[d]; CA[d]=xr[3+d]; Ct[d]=xr[6+d]; Oa[d]=xr[9+d]; }
        #pragma unroll
        for (int d = 0; d < 3; d++) {
            float s = __fadd_rn(__fadd_rn(__fadd_rn(Na[d], CA[d]), Ct[d]), Oa[d]);
            g_Xc[nlin*3 + d] = __fmul_rn(s, 0.25f);
        }
        float b1[3], b2[3], b3[3], v0[3];
        #pragma unroll
        for (int d = 0; d < 3; d++) {
            b1[d] = CA[d] - Na[d];
            b2[d] = Ct[d] - CA[d];
            b3[d] = Oa[d] - Ct[d];
            v0[d] = Na[d] - CA[d];
        }
        float nb2 = sqrtf(b2[0]*b2[0] + b2[1]*b2[1] + b2[2]*b2[2]);
        float u[3];
        #pragma unroll
        for (int d = 0; d < 3; d++) u[d] = b2[d] / (nb2 + EPSF);
        float dotv = v0[0]*u[0] + v0[1]*u[1] + v0[2]*u[2];
        float t[3];
        #pragma unroll
        for (int d = 0; d < 3; d++) t[d] = v0[d] - dotv * u[d];
        float nt = sqrtf(t[0]*t[0] + t[1]*t[1] + t[2]*t[2]);
        float v[3];
        #pragma unroll
        for (int d = 0; d < 3; d++) v[d] = t[d] / (nt + EPSF);
        float w[3];
        w[0] = u[1]*v[2] - u[2]*v[1];
        w[1] = u[2]*v[0] - u[0]*v[2];
        w[2] = u[0]*v[1] - u[1]*v[0];
        #pragma unroll
        for (int d = 0; d < 3; d++) {
            g_R[nlin*9 + d*3 + 0] = u[d];
            g_R[nlin*9 + d*3 + 1] = v[d];
            g_R[nlin*9 + d*3 + 2] = w[d];
        }
        float nb1 = sqrtf(b1[0]*b1[0] + b1[1]*b1[1] + b1[2]*b1[2]);
        float nb3 = sqrtf(b3[0]*b3[0] + b3[1]*b3[1] + b3[2]*b3[2]);
        #pragma unroll
        for (int d = 0; d < 3; d++) {
            s_feat[warp][0 + d] = b1[d] / (nb1 + EPSF);
            s_feat[warp][4 + d] = b2[d] / (nb2 + EPSF);
            s_feat[warp][8 + d] = b3[d] / (nb3 + EPSF);
        }
        s_feat[warp][3]  = logf(nb1 + EPSF);
        s_feat[warp][7]  = logf(nb2 + EPSF);
        s_feat[warp][11] = logf(nb3 + EPSF);
        float mk = (C[nlin] > 0) ? 1.0f : 0.0f;
        s_mask[warp] = mk;
        g_maski[nlin] = mk;
    }
    __syncwarp();

    float f[12];
    #pragma unroll
    for (int i = 0; i < 12; i++) f[i] = s_feat[warp][i];
    float mk = s_mask[warp];
    #pragma unroll
    for (int r = 0; r < 8; r++) {
        int c = lane + r * 32;
        float acc = bn[c];
        #pragma unroll
        for (int ff = 0; ff < NFI; ff++) acc += f[ff] * Wn[ff*DN + c];
        float v = acc * mk;
        g_nodeh [(size_t)nlin*DN + c] = v;
        g_nodehr[(size_t)nlin*DN + c] = rtf(v);
    }
}

// ---------------- 2) kNN: warp-per-node, exact semantics ----------------
__global__ __launch_bounds__(128) void knn_kernel(const int* __restrict__ C)
{
    __shared__ float s_d2[4][NN];
    int wid = threadIdx.x >> 5;
    int lane = threadIdx.x & 31;
    int nlin = blockIdx.x * 4 + wid;
    int b = nlin >> 11;
    int n = nlin & (NN - 1);

    float xi0 = g_Xc[nlin*3+0], xi1 = g_Xc[nlin*3+1], xi2 = g_Xc[nlin*3+2];
    const int* Cb = C + b*NN;
    for (int j = lane; j < NN; j += 32) {
        float dx = __fadd_rn(xi0, -g_Xc[(size_t)(b*NN + j)*3 + 0]);
        float dy = __fadd_rn(xi1, -g_Xc[(size_t)(b*NN + j)*3 + 1]);
        float dz = __fadd_rn(xi2, -g_Xc[(size_t)(b*NN + j)*3 + 2]);
        float d2 = __fadd_rn(__fadd_rn(__fmul_rn(dx,dx), __fmul_rn(dy,dy)), __fmul_rn(dz,dz));
        if (Cb[j] <= 0) d2 = __fadd_rn(d2, BIGF);
        if (j == n)     d2 = __fadd_rn(d2, BIGF);
        s_d2[wid][j] = d2;
    }
    __syncwarp();

    float mi = g_maski[nlin];
    float cnt = 0.0f;
    for (int kk = 0; kk < KNB; kk++) {
        float bv = FLTMAX; int bi = 0x7fffffff;
        #pragma unroll 4
        for (int j = lane; j < NN; j += 32) {
            float v = s_d2[wid][j];
            if (v < bv || (v == bv && j < bi)) { bv = v; bi = j; }
        }
        #pragma unroll
        for (int off = 16; off > 0; off >>= 1) {
            float v2 = __shfl_down_sync(0xffffffffu, bv, off);
            int   i2 = __shfl_down_sync(0xffffffffu, bi, off);
            if (v2 < bv || (v2 == bv && i2 < bi)) { bv = v2; bi = i2; }
        }
        bi = __shfl_sync(0xffffffffu, bi, 0);
        if (lane == 0) {
            int e = nlin*KNB + kk;
            g_eidx[e] = bi;
            float mj = (Cb[bi] > 0) ? 1.0f : 0.0f;
            float mij = mi * mj;
            g_maskij[e] = mij;
            cnt += mij;
            s_d2[wid][bi] = FLTMAX;
        }
        __syncwarp();
    }
    if (lane == 0) { g_cnt[nlin] = cnt; g_denom[nlin] = cnt + EPSF; }
}

// ---------------- 3) edge features + edge_h init ----------------
__global__ void edge_feat_kernel(const float* __restrict__ We, const float* __restrict__ be)
{
    __shared__ float s_feat[KNB][EFI];
    int nlin = blockIdx.x;
    int b = nlin >> 11;
    int tid = threadIdx.x;

    if (tid < KNB) {
        int e = nlin*KNB + tid;
        int j = g_eidx[e];
        int jl = b*NN + j;
        float dv[3];
        #pragma unroll
        for (int d = 0; d < 3; d++) dv[d] = g_Xc[jl*3+d] - g_Xc[nlin*3+d];
        float dist = sqrtf(dv[0]*dv[0] + dv[1]*dv[1] + dv[2]*dv[2]);
        float Ri[9], Rj[9];
        #pragma unroll
        for (int q = 0; q < 9; q++) { Ri[q] = g_R[nlin*9+q]; Rj[q] = g_R[jl*9+q]; }
        float inv = 1.0f / (dist + EPSF);
        #pragma unroll
        for (int c = 0; c < 3; c++) {
            float loc = Ri[0*3+c]*dv[0] + Ri[1*3+c]*dv[1] + Ri[2*3+c]*dv[2];
            s_feat[tid][16 + c] = loc * inv;
        }
        #pragma unroll
        for (int ee = 0; ee < 3; ee++)
            #pragma unroll
            for (int ff = 0; ff < 3; ff++) {
                float r = Ri[0*3+ee]*Rj[0*3+ff] + Ri[1*3+ee]*Rj[1*3+ff] + Ri[2*3+ee]*Rj[2*3+ff];
                s_feat[tid][19 + ee*3 + ff] = r;
            }
        #pragma unroll
        for (int mc = 0; mc < 16; mc++) {
            float cm = (float)(20.0 * mc / 15.0);
            float z = (dist - cm) * 0.8f;
            s_feat[tid][mc] = expf(-z*z);
        }
    }
    __syncthreads();

    for (int idx = tid; idx < KNB*DE; idx += blockDim.x) {
        int k = idx >> 7;
        int c = idx & 127;
        int e = nlin*KNB + k;
        float acc = be[c];
        #pragma unroll
        for (int f = 0; f < EFI; f++) acc += s_feat[k][f] * We[f*DE + c];
        float v = acc * g_maskij[e];
        g_edgeh [(size_t)e*DE + c] = v;
        g_edgehr[(size_t)e*DE + c] = rtf(v);
    }
}

// ---------------- 4) tf32 TC GEMM, 4-stage cp.async, pre-rounded inputs ----------------
// A and W must already be tf32-rounded bit patterns (fed to MMA without cvt).
// MODE 0: out[z-slab] = A @ W[z-slab]                           (raw fp32 store)
// MODE 1: out = softplus(A@W + bias + Yi[i] + Zj[j]) (RND: round stored value)
// MODE 2: edge_h = (edge_h + A@W + bias)*maskij  + rounded shadow store
// MODE 3: node_h = (node_h + (A@W + cnt*bias)/denom)*mask_i + rounded shadow
#define MM_ST 4
#define MM_AS (128*20)
#define MM_BS (16*132)
#define MM_SMEM ((MM_ST*(MM_AS+MM_BS))*4)

template<int KD, int NF, int MODE, int RND>
__global__ __launch_bounds__(256, 2) void mm_tc(
    const float* __restrict__ A, const float* __restrict__ W,
    const float* __restrict__ bias,
    const float* __restrict__ Yi, const float* __restrict__ Zj,
    float* __restrict__ out, float* __restrict__ out2)
{
    constexpr int CH = KD / 16;
    extern __shared__ float smem_dyn[];
    float* Asm = smem_dyn;
    float* Bsm = smem_dyn + MM_ST*MM_AS;

    const int tid  = threadIdx.x;
    const int lane = tid & 31;
    const int wid  = tid >> 5;
    const int wm   = wid & 1;
    const int wn   = wid >> 1;

    const int rowBase = blockIdx.x * 128;
    const int n0 = blockIdx.y * 128;

    const float* Wp = W;
    float* outp = out;
    if (MODE == 0) {
        Wp   = W   + (size_t)blockIdx.z * KD * NF;
        outp = out + (size_t)blockIdx.z * NNODE * NF;
    }

    const int laR = tid >> 1, laK = (tid & 1) * 8;
    const int lbK = tid >> 4, lbN = (tid & 15) * 8;
    const float* Ag = A  + (size_t)(rowBase + laR) * KD + laK;
    const float* Wg = Wp + (size_t)lbK * NF + n0 + lbN;

    const unsigned sa = (unsigned)__cvta_generic_to_shared(Asm) + (laR*20 + laK)*4;
    const unsigned sb = (unsigned)__cvta_generic_to_shared(Bsm) + (lbK*132 + lbN)*4;

    #pragma unroll
    for (int s = 0; s < MM_ST-1; s++) {
        cp16(sa + s*MM_AS*4,      Ag + s*16);
        cp16(sa + s*MM_AS*4 + 16, Ag + s*16 + 4);
        cp16(sb + s*MM_BS*4,      Wg + (size_t)s*16*NF);
        cp16(sb + s*MM_BS*4 + 16, Wg + (size_t)s*16*NF + 4);
        CP_COMMIT();
    }

    float acc[4][4][4];
    #pragma unroll
    for (int i = 0; i < 4; i++)
        #pragma unroll
        for (int j = 0; j < 4; j++)
            #pragma unroll
            for (int q = 0; q < 4; q++) acc[i][j][q] = 0.0f;

    #pragma unroll 1
    for (int c = 0; c < CH; c++) {
        CP_WAIT2();
        __syncthreads();

        if (c + MM_ST-1 < CH) {
            const int slot = (c + MM_ST-1) & (MM_ST-1);
            const int cc = c + MM_ST-1;
            cp16(sa + slot*MM_AS*4,      Ag + cc*16);
            cp16(sa + slot*MM_AS*4 + 16, Ag + cc*16 + 4);
            cp16(sb + slot*MM_BS*4,      Wg + (size_t)cc*16*NF);
            cp16(sb + slot*MM_BS*4 + 16, Wg + (size_t)cc*16*NF + 4);
        }
        CP_COMMIT();

        const unsigned* As = (const unsigned*)(Asm + (c & (MM_ST-1)) * MM_AS);
        const unsigned* Bs = (const unsigned*)(Bsm + (c & (MM_ST-1)) * MM_BS);

        #pragma unroll
        for (int kk = 0; kk < 2; kk++) {
            const int kb = kk * 8;
            unsigned a[4][4], bq[4][2];
            #pragma unroll
            for (int mt = 0; mt < 4; mt++) {
                int r0 = wm*64 + mt*16 + (lane >> 2);
                a[mt][0] = As[(r0  )*20 + kb + (lane & 3)];
                a[mt][1] = As[(r0+8)*20 + kb + (lane & 3)];
                a[mt][2] = As[(r0  )*20 + kb + (lane & 3) + 4];
                a[mt][3] = As[(r0+8)*20 + kb + (lane & 3) + 4];
            }
            #pragma unroll
            for (int nt = 0; nt < 4; nt++) {
                int cc2 = wn*32 + nt*8 + (lane >> 2);
                bq[nt][0] = Bs[(kb + (lane & 3)    )*132 + cc2];
                bq[nt][1] = Bs[(kb + (lane & 3) + 4)*132 + cc2];
            }
            #pragma unroll
            for (int mt = 0; mt < 4; mt++)
                #pragma unroll
                for (int nt = 0; nt < 4; nt++)
                    mma8(acc[mt][nt], a[mt], bq[nt]);
        }
        // no trailing barrier: slot reuse is fenced by the next iteration's sync
    }

    // ---------------- epilogue ----------------
    #pragma unroll
    for (int mt = 0; mt < 4; mt++) {
        #pragma unroll
        for (int h = 0; h < 2; h++) {
            const int r = wm*64 + mt*16 + (lane >> 2) + h*8;
            const int grow = rowBase + r;

            const float* yip = nullptr; const float* zjp = nullptr;
            float mij = 0.f, dn = 1.f, mi = 0.f, cn = 0.f;
            const float* nhp = nullptr; const float* ehp = nullptr;
            if (MODE == 1) {
                int nlin = grow / KNB;
                int b = nlin >> 11;
                yip = Yi + (size_t)nlin * NF + n0;
                zjp = Zj + (size_t)(b*NN + g_eidx[grow]) * NF + n0;
            } else if (MODE == 2) {
                mij = g_maskij[grow];
                ehp = g_edgeh + (size_t)grow * DE + n0;
            } else if (MODE == 3) {
                dn = g_denom[grow]; mi = g_maski[grow]; cn = g_cnt[grow];
                nhp = g_nodeh + (size_t)grow * DN + n0;
            }

            float* op  = outp + (size_t)grow * NF + n0;
            float* op2 = (MODE == 2 || MODE == 3) ? (out2 + (size_t)grow * NF + n0) : nullptr;
            #pragma unroll
            for (int nt = 0; nt < 4; nt++) {
                const int c0 = wn*32 + nt*8 + 2*(lane & 3);
                float v0 = acc[mt][nt][h*2 + 0];
                float v1 = acc[mt][nt][h*2 + 1];
                if (MODE == 0) {
                    *(float2*)(op + c0) = make_float2(v0, v1);
                } else if (MODE == 1) {
                    float2 bsv = *(const float2*)(bias + n0 + c0);
                    float2 yv  = *(const float2*)(yip + c0);
                    float2 zv  = *(const float2*)(zjp + c0);
                    v0 = softplus_f(v0 + bsv.x + yv.x + zv.x);
                    v1 = softplus_f(v1 + bsv.y + yv.y + zv.y);
                    if (RND) { v0 = rtf(v0); v1 = rtf(v1); }
                    *(float2*)(op + c0) = make_float2(v0, v1);
                } else if (MODE == 2) {
                    float2 bsv = *(const float2*)(bias + n0 + c0);
                    float2 ev  = *(const float2*)(ehp + c0);
                    v0 = (ev.x + v0 + bsv.x) * mij;
                    v1 = (ev.y + v1 + bsv.y) * mij;
                    *(float2*)(op  + c0) = make_float2(v0, v1);
                    *(float2*)(op2 + c0) = make_float2(rtf(v0), rtf(v1));
                } else {
                    float2 bsv = *(const float2*)(bias + n0 + c0);
                    float2 nv  = *(const float2*)(nhp + c0);
                    v0 = (nv.x + (v0 + cn*bsv.x) / dn) * mi;
                    v1 = (nv.y + (v1 + cn*bsv.y) / dn) * mi;
                    *(float2*)(op  + c0) = make_float2(v0, v1);
                    *(float2*)(op2 + c0) = make_float2(rtf(v0), rtf(v1));
                }
            }
        }
    }
}

// ---------------- 5) masked k-sum of t1 per node (rounded at write) ----------------
__global__ void ksum_kernel()
{
    __shared__ float sm[KNB];
    int nlin = blockIdx.x;
    int c = threadIdx.x;
    if (c < KNB) sm[c] = g_maskij[nlin*KNB + c];
    __syncthreads();
    float s = 0.0f;
    #pragma unroll
    for (int k = 0; k < KNB; k++)
        s += sm[k] * g_t1[(size_t)(nlin*KNB + k)*DN + c];
    g_ksum[(size_t)nlin*DN + c] = rtf(s);
}

// ---------------- 6) pack outputs (float4) ----------------
__global__ void copy_out_kernel(float4* __restrict__ out)
{
    const int S0 = NNODE*DN/4;
    const int S1 = ETOT*DE/4;
    const int S2 = ETOT/4;
    const int S3 = NNODE/4;
    const int TOT = S0 + S1 + S2 + S3 + ETOT/4;
    const float4* nh = (const float4*)g_nodeh;
    const float4* eh = (const float4*)g_edgeh;
    const int4*   ei = (const int4*)g_eidx;
    const float4* mi = (const float4*)g_maski;
    const float4* mj = (const float4*)g_maskij;
    for (int i = blockIdx.x*blockDim.x + threadIdx.x; i < TOT; i += gridDim.x*blockDim.x) {
        float4 v;
        if (i < S0)                    v = nh[i];
        else if (i < S0+S1)            v = eh[i - S0];
        else if (i < S0+S1+S2) {
            int4 t = ei[i - S0 - S1];
            v = make_float4((float)t.x, (float)t.y, (float)t.z, (float)t.w);
        }
        else if (i < S0+S1+S2+S3)      v = mi[i - S0 - S1 - S2];
        else                           v = mj[i - S0 - S1 - S2 - S3];
        out[i] = v;
    }
}

// ---------------- launch ----------------
extern "C" void kernel_launch(void* const* d_in, const int* in_sizes, int n_in,
                              void* d_out, int out_size)
{
    const float* X    = (const float*)d_in[0];
    const int*   C    = (const int*)  d_in[1];
    const float* Wn   = (const float*)d_in[2];
    const float* bn   = (const float*)d_in[3];
    const float* We   = (const float*)d_in[4];
    const float* be   = (const float*)d_in[5];
    const float* Wm1  = (const float*)d_in[6];
    const float* bm1  = (const float*)d_in[7];
    const float* Wm2  = (const float*)d_in[8];
    const float* bm2  = (const float*)d_in[9];
    const float* Wue1 = (const float*)d_in[10];
    const float* bue1 = (const float*)d_in[11];
    const float* Wue2 = (const float*)d_in[12];
    const float* bue2 = (const float*)d_in[13];

    cudaFuncSetAttribute(mm_tc<256,256,0,0>, cudaFuncAttributeMaxDynamicSharedMemorySize, MM_SMEM);
    cudaFuncSetAttribute(mm_tc<256,128,0,0>, cudaFuncAttributeMaxDynamicSharedMemorySize, MM_SMEM);
    cudaFuncSetAttribute(mm_tc<128,256,1,0>, cudaFuncAttributeMaxDynamicSharedMemorySize, MM_SMEM);
    cudaFuncSetAttribute(mm_tc<128,128,1,1>, cudaFuncAttributeMaxDynamicSharedMemorySize, MM_SMEM);
    cudaFuncSetAttribute(mm_tc<256,256,3,0>, cudaFuncAttributeMaxDynamicSharedMemorySize, MM_SMEM);
    cudaFuncSetAttribute(mm_tc<128,128,2,0>, cudaFuncAttributeMaxDynamicSharedMemorySize, MM_SMEM);

    round_w_kernel<<<512, 256>>>(Wm1, Wue1, Wm2, Wue2);
    frame_kernel<<<NNODE/8, 256>>>(X, C, Wn, bn);
    knn_kernel<<<NNODE/4, 128>>>(C);
    edge_feat_kernel<<<NNODE, 128>>>(We, be);

    float* Ym;  cudaGetSymbolAddress((void**)&Ym, g_Ym);
    float* Ye;  cudaGetSymbolAddress((void**)&Ye, g_Ye);
    float* T1;  cudaGetSymbolAddress((void**)&T1, g_t1);
    float* T2;  cudaGetSymbolAddress((void**)&T2, g_t2);
    float* Eh;  cudaGetSymbolAddress((void**)&Eh, g_edgeh);
    float* Ehr; cudaGetSymbolAddress((void**)&Ehr, g_edgehr);
    float* Nh;  cudaGetSymbolAddress((void**)&Nh, g_nodeh);
    float* Nhr; cudaGetSymbolAddress((void**)&Nhr, g_nodehr);
    float* Ks;  cudaGetSymbolAddress((void**)&Ks, g_ksum);
    float* Wr;  cudaGetSymbolAddress((void**)&Wr, g_Wr);

    const int MD = 2*DN + DE;  // 640
    for (int l = 0; l < NL; l++) {
        const float* Wm1l  = Wr + WR_M1  + (size_t)l*MD*DN;
        const float* Wue1l = Wr + WR_UE1 + (size_t)l*MD*DE;
        const float* Wm2l  = Wr + WR_M2  + (size_t)l*DN*DN;
        const float* Wue2l = Wr + WR_UE2 + (size_t)l*DE*DE;

        mm_tc<256, 256, 0, 0><<<dim3(NNODE/128, 2, 2), 256, MM_SMEM>>>(
            Nhr, Wm1l,  nullptr, nullptr, nullptr, Ym, nullptr);
        mm_tc<256, 128, 0, 0><<<dim3(NNODE/128, 1, 2), 256, MM_SMEM>>>(
            Nhr, Wue1l, nullptr, nullptr, nullptr, Ye, nullptr);
        mm_tc<128, 256, 1, 0><<<dim3(ETOT/128, 2), 256, MM_SMEM>>>(
            Ehr, Wm1l  + (size_t)2*DN*DN, bm1  + l*DN, Ym, Ym + (size_t)NNODE*DN, T1, nullptr);
        mm_tc<128, 128, 1, 1><<<dim3(ETOT/128, 1), 256, MM_SMEM>>>(
            Ehr, Wue1l + (size_t)2*DN*DE, bue1 + l*DE, Ye, Ye + (size_t)NNODE*DE, T2, nullptr);
        ksum_kernel<<<NNODE, DN>>>();
        mm_tc<256, 256, 3, 0><<<dim3(NNODE/128, 2), 256, MM_SMEM>>>(
            Ks, Wm2l, bm2 + l*DN, nullptr, nullptr, Nh, Nhr);
        mm_tc<128, 128, 2, 0><<<dim3(ETOT/128, 1), 256, MM_SMEM>>>(
            T2, Wue2l, bue2 + l*DE, nullptr, nullptr, Eh, Ehr);
    }

    copy_out_kernel<<<2048, 256>>>((float4*)d_out);
}

// round 6
// speedup vs baseline: 5.9564x; 1.1395x over previous
#include <cuda_runtime.h>
#include <math.h>

// ---------------- problem constants ----------------
#define BB   2
#define NN   2048
#define KNB  30
#define DN   256
#define DE   128
#define NL   3
#define NFI  12
#define EFI  28
#define ETOT (BB*NN*KNB)  // 122880
#define NNODE (BB*NN)     // 4096
#define EPSF 1e-6f
#define BIGF 1e9f
#define FLTMAX 3.402823466e38f

#define S0OUT (NNODE*DN)        // 1048576
#define S1OUT (ETOT*DE)         // 15728640

// ---------------- scratch ----------------
__device__ float g_nodeh [NNODE*DN];
__device__ float g_nodehr[NNODE*DN];      // tf32-rounded shadow
__device__ float g_edgeh [ETOT*DE];
__device__ float g_edgehr[ETOT*DE];       // tf32-rounded shadow
__device__ int   g_eidx [ETOT];
__device__ float g_maski[NNODE];
__device__ float g_maskij[ETOT];
__device__ float g_denom[NNODE];
__device__ float g_cnt  [NNODE];
__device__ float g_R  [NNODE*9];
__device__ float g_Xc [NNODE*3];
__device__ float g_t2 [ETOT*DE];          // rounded at write (MMA input)
__device__ float g_Ym [2*NNODE*DN];
__device__ float g_Ye [2*NNODE*DE];
__device__ float g_ksum[NNODE*DN];        // atomic fp32 accum, rounded in-place after
__device__ float g_featr[ETOT*32];        // rounded edge features (k=28 padded to 32)

// rounded-weight arena layout
#define WR_CAT  0
#define WR_E1M  (3*2*256*384)             // 589824
#define WR_E1E  (WR_E1M + 3*128*256)      // 688128
#define WR_M2   (WR_E1E + 3*128*128)      // 737280
#define WR_UE2  (WR_M2  + 3*256*256)      // 933888
#define WR_WE   (WR_UE2 + 3*128*128)      // 983040
#define WR_TOT  (WR_WE  + 32*128)         // 987136
__device__ float g_Wr[WR_TOT];

__device__ __forceinline__ float softplus_f(float x) {
    return fmaxf(x, 0.0f) + log1pf(expf(-fabsf(x)));
}
__device__ __forceinline__ unsigned f2tf(float x) {
    unsigned r; asm("cvt.rna.tf32.f32 %0, %1;" : "=r"(r) : "f"(x)); return r;
}
__device__ __forceinline__ float rtf(float x) { return __uint_as_float(f2tf(x)); }
__device__ __forceinline__ void mma8(float* c, const unsigned* a, const unsigned* b) {
    asm volatile(
        "mma.sync.aligned.m16n8k8.row.col.f32.tf32.tf32.f32 "
        "{%0,%1,%2,%3},{%4,%5,%6,%7},{%8,%9},{%0,%1,%2,%3};"
        : "+f"(c[0]), "+f"(c[1]), "+f"(c[2]), "+f"(c[3])
        : "r"(a[0]), "r"(a[1]), "r"(a[2]), "r"(a[3]), "r"(b[0]), "r"(b[1]));
}
__device__ __forceinline__ void cp16(unsigned dst, const float* src) {
    asm volatile("cp.async.cg.shared.global [%0], [%1], 16;" :: "r"(dst), "l"(src));
}
#define CP_COMMIT() asm volatile("cp.async.commit_group;")
#define CP_WAIT2()  asm volatile("cp.async.wait_group 2;")

// ---------------- 0) round + repack all weight tensors ----------------
__global__ void round_w_kernel(const float* __restrict__ Wm1, const float* __restrict__ Wue1,
                               const float* __restrict__ Wm2, const float* __restrict__ Wue2,
                               const float* __restrict__ We)
{
    for (int i = blockIdx.x*blockDim.x + threadIdx.x; i < WR_TOT; i += gridDim.x*blockDim.x) {
        float v;
        if (i < WR_E1M) {                       // node-part cat: [l][z][k<256][n<384]
            int l = i / 196608, r = i % 196608;
            int z = r / 98304,  q = r % 98304;
            int k = q / 384,    n = q % 384;
            v = (n < 256) ? Wm1 [(size_t)l*163840 + (z*256 + k)*256 + n]
                          : Wue1[(size_t)l*81920  + (z*256 + k)*128 + (n - 256)];
        } else if (i < WR_E1E) {                // edge-part of Wm1: rows 512..639
            int r = i - WR_E1M;
            int l = r / 32768, q = r % 32768;
            int k = q / 256,   n = q % 256;
            v = Wm1[(size_t)l*163840 + (512 + k)*256 + n];
        } else if (i < WR_M2) {                 // edge-part of Wue1
            int r = i - WR_E1E;
            int l = r / 16384, q = r % 16384;
            int k = q / 128,   n = q % 128;
            v = Wue1[(size_t)l*81920 + (512 + k)*128 + n];
        } else if (i < WR_UE2) {
            v = Wm2[i - WR_M2];
        } else if (i < WR_WE) {
            v = Wue2[i - WR_UE2];
        } else {                                // We padded 28->32 rows
            int r = i - WR_WE;
            int k = r / 128, n = r % 128;
            v = (k < EFI) ? We[k*128 + n] : 0.0f;
        }
        g_Wr[i] = rtf(v);
    }
}

// ---------------- 1) per-node frame, features, node_h init ----------------
__global__ void frame_kernel(const float* __restrict__ X, const int* __restrict__ C,
                             const float* __restrict__ Wn, const float* __restrict__ bn)
{
    __shared__ float s_feat[8][12];
    __shared__ float s_mask[8];
    int warp = threadIdx.x >> 5;
    int lane = threadIdx.x & 31;
    int nlin = blockIdx.x * 8 + warp;

    if (lane == 0) {
        const float* xr = X + (size_t)nlin * 12;
        float Na[3], CA[3], Ct[3], Oa[3];
        #pragma unroll
        for (int d = 0; d < 3; d++) { Na[d]=xr[d]; CA[d]=xr[3+d]; Ct[d]=xr[6+d]; Oa[d]=xr[9+d]; }
        #pragma unroll
        for (int d = 0; d < 3; d++) {
            float s = __fadd_rn(__fadd_rn(__fadd_rn(Na[d], CA[d]), Ct[d]), Oa[d]);
            g_Xc[nlin*3 + d] = __fmul_rn(s, 0.25f);
        }
        float b1[3], b2[3], b3[3], v0[3];
        #pragma unroll
        for (int d = 0; d < 3; d++) {
            b1[d] = CA[d] - Na[d];
            b2[d] = Ct[d] - CA[d];
            b3[d] = Oa[d] - Ct[d];
            v0[d] = Na[d] - CA[d];
        }
        float nb2 = sqrtf(b2[0]*b2[0] + b2[1]*b2[1] + b2[2]*b2[2]);
        float u[3];
        #pragma unroll
        for (int d = 0; d < 3; d++) u[d] = b2[d] / (nb2 + EPSF);
        float dotv = v0[0]*u[0] + v0[1]*u[1] + v0[2]*u[2];
        float t[3];
        #pragma unroll
        for (int d = 0; d < 3; d++) t[d] = v0[d] - dotv * u[d];
        float nt = sqrtf(t[0]*t[0] + t[1]*t[1] + t[2]*t[2]);
        float v[3];
        #pragma unroll
        for (int d = 0; d < 3; d++) v[d] = t[d] / (nt + EPSF);
        float w[3];
        w[0] = u[1]*v[2] - u[2]*v[1];
        w[1] = u[2]*v[0] - u[0]*v[2];
        w[2] = u[0]*v[1] - u[1]*v[0];
        #pragma unroll
        for (int d = 0; d < 3; d++) {
            g_R[nlin*9 + d*3 + 0] = u[d];
            g_R[nlin*9 + d*3 + 1] = v[d];
            g_R[nlin*9 + d*3 + 2] = w[d];
        }
        float nb1 = sqrtf(b1[0]*b1[0] + b1[1]*b1[1] + b1[2]*b1[2]);
        float nb3 = sqrtf(b3[0]*b3[0] + b3[1]*b3[1] + b3[2]*b3[2]);
        #pragma unroll
        for (int d = 0; d < 3; d++) {
            s_feat[warp][0 + d] = b1[d] / (nb1 + EPSF);
            s_feat[warp][4 + d] = b2[d] / (nb2 + EPSF);
            s_feat[warp][8 + d] = b3[d] / (nb3 + EPSF);
        }
        s_feat[warp][3]  = logf(nb1 + EPSF);
        s_feat[warp][7]  = logf(nb2 + EPSF);
        s_feat[warp][11] = logf(nb3 + EPSF);
        float mk = (C[nlin] > 0) ? 1.0f : 0.0f;
        s_mask[warp] = mk;
        g_maski[nlin] = mk;
    }
    __syncwarp();

    float f[12];
    #pragma unroll
    for (int i = 0; i < 12; i++) f[i] = s_feat[warp][i];
    float mk = s_mask[warp];
    #pragma unroll
    for (int r = 0; r < 8; r++) {
        int c = lane + r * 32;
        float acc = bn[c];
        #pragma unroll
        for (int ff = 0; ff < NFI; ff++) acc += f[ff] * Wn[ff*DN + c];
        float v = acc * mk;
        g_nodeh [(size_t)nlin*DN + c] = v;
        g_nodehr[(size_t)nlin*DN + c] = rtf(v);
    }
}

// ---------------- 2) kNN: warp-per-node, exact semantics ----------------
__global__ __launch_bounds__(128) void knn_kernel(const int* __restrict__ C)
{
    __shared__ float s_d2[4][NN];
    int wid = threadIdx.x >> 5;
    int lane = threadIdx.x & 31;
    int nlin = blockIdx.x * 4 + wid;
    int b = nlin >> 11;
    int n = nlin & (NN - 1);

    float xi0 = g_Xc[nlin*3+0], xi1 = g_Xc[nlin*3+1], xi2 = g_Xc[nlin*3+2];
    const int* Cb = C + b*NN;
    for (int j = lane; j < NN; j += 32) {
        float dx = __fadd_rn(xi0, -g_Xc[(size_t)(b*NN + j)*3 + 0]);
        float dy = __fadd_rn(xi1, -g_Xc[(size_t)(b*NN + j)*3 + 1]);
        float dz = __fadd_rn(xi2, -g_Xc[(size_t)(b*NN + j)*3 + 2]);
        float d2 = __fadd_rn(__fadd_rn(__fmul_rn(dx,dx), __fmul_rn(dy,dy)), __fmul_rn(dz,dz));
        if (Cb[j] <= 0) d2 = __fadd_rn(d2, BIGF);
        if (j == n)     d2 = __fadd_rn(d2, BIGF);
        s_d2[wid][j] = d2;
    }
    __syncwarp();

    float mi = g_maski[nlin];
    float cnt = 0.0f;
    for (int kk = 0; kk < KNB; kk++) {
        float bv = FLTMAX; int bi = 0x7fffffff;
        #pragma unroll 4
        for (int j = lane; j < NN; j += 32) {
            float v = s_d2[wid][j];
            if (v < bv || (v == bv && j < bi)) { bv = v; bi = j; }
        }
        #pragma unroll
        for (int off = 16; off > 0; off >>= 1) {
            float v2 = __shfl_down_sync(0xffffffffu, bv, off);
            int   i2 = __shfl_down_sync(0xffffffffu, bi, off);
            if (v2 < bv || (v2 == bv && i2 < bi)) { bv = v2; bi = i2; }
        }
        bi = __shfl_sync(0xffffffffu, bi, 0);
        if (lane == 0) {
            int e = nlin*KNB + kk;
            g_eidx[e] = bi;
            float mj = (Cb[bi] > 0) ? 1.0f : 0.0f;
            float mij = mi * mj;
            g_maskij[e] = mij;
            cnt += mij;
            s_d2[wid][bi] = FLTMAX;
        }
        __syncwarp();
    }
    if (lane == 0) { g_cnt[nlin] = cnt; g_denom[nlin] = cnt + EPSF; }
}

// ---------------- 3) edge features -> g_featr (rounded, padded to 32) ----------------
__global__ __launch_bounds__(128) void feat_kernel()
{
    int e = blockIdx.x * 128 + threadIdx.x;   // grid = ETOT/128
    int nlin = e / KNB;
    int b = nlin >> 11;
    int j = g_eidx[e];
    int jl = b*NN + j;

    float dv[3];
    #pragma unroll
    for (int d = 0; d < 3; d++) dv[d] = g_Xc[jl*3+d] - g_Xc[nlin*3+d];
    float dist = sqrtf(dv[0]*dv[0] + dv[1]*dv[1] + dv[2]*dv[2]);
    float Ri[9], Rj[9];
    #pragma unroll
    for (int q = 0; q < 9; q++) { Ri[q] = g_R[nlin*9+q]; Rj[q] = g_R[jl*9+q]; }

    float f[32];
    #pragma unroll
    for (int mc = 0; mc < 16; mc++) {
        float cm = (float)(20.0 * mc / 15.0);
        float z = (dist - cm) * 0.8f;
        f[mc] = expf(-z*z);
    }
    float inv = 1.0f / (dist + EPSF);
    #pragma unroll
    for (int c = 0; c < 3; c++) {
        float loc = Ri[0*3+c]*dv[0] + Ri[1*3+c]*dv[1] + Ri[2*3+c]*dv[2];
        f[16 + c] = loc * inv;
    }
    #pragma unroll
    for (int ee = 0; ee < 3; ee++)
        #pragma unroll
        for (int ff = 0; ff < 3; ff++)
            f[19 + ee*3 + ff] = Ri[0*3+ee]*Rj[0*3+ff] + Ri[1*3+ee]*Rj[1*3+ff] + Ri[2*3+ee]*Rj[2*3+ff];
    f[28] = f[29] = f[30] = f[31] = 0.0f;

    float4* op = (float4*)(g_featr + (size_t)e*32);
    #pragma unroll
    for (int q = 0; q < 8; q++)
        op[q] = make_float4(rtf(f[q*4]), rtf(f[q*4+1]), rtf(f[q*4+2]), rtf(f[q*4+3]));
}

// ---------------- helpers ----------------
__global__ void zero_ksum_kernel()
{
    float4* p = (float4*)g_ksum;
    for (int i = blockIdx.x*blockDim.x + threadIdx.x; i < NNODE*DN/4; i += gridDim.x*blockDim.x)
        p[i] = make_float4(0.f, 0.f, 0.f, 0.f);
}
__global__ void round_ksum_kernel()
{
    float4* p = (float4*)g_ksum;
    for (int i = blockIdx.x*blockDim.x + threadIdx.x; i < NNODE*DN/4; i += gridDim.x*blockDim.x) {
        float4 v = p[i];
        p[i] = make_float4(rtf(v.x), rtf(v.y), rtf(v.z), rtf(v.w));
    }
}
__global__ void copy_tail_kernel(float* __restrict__ out)
{
    const int S2 = ETOT, S3 = NNODE;
    const int TOT = ETOT + NNODE + ETOT;
    for (int i = blockIdx.x*blockDim.x + threadIdx.x; i < TOT; i += gridDim.x*blockDim.x) {
        float v;
        if (i < S2)           v = (float)g_eidx[i];
        else if (i < S2+S3)   v = g_maski[i - S2];
        else                  v = g_maskij[i - S2 - S3];
        out[i] = v;
    }
}

// ---------------- 4) tf32 TC GEMM, 4-stage cp.async, pre-rounded inputs ----------------
// MODE 1: t2 = rtf(softplus(A@W + bias + Ye_i + Ze_j))          (e-path stage-1)
// MODE 2: edge_h = (edge_h + A@W + bias)*maskij  [FLG: +rounded shadow]
// MODE 3: node_h = (node_h + (A@W + cnt*bias)/denom)*mask_i [FLG: +shadow]
// MODE 4: edge_h init = (A@W + bias)*maskij -> out(exact) + out2(rounded)
// MODE 5: m-path stage-1: masked softplus -> smem reduce -> atomic g_ksum
// MODE 6: node precompute cat: cols<256 -> Ym[z], cols>=256 -> Ye[z]
#define MM_ST 4
#define MM_AS (128*20)
#define MM_BS (16*132)
#define MM_SMEM ((MM_ST*(MM_AS+MM_BS))*4)

template<int KD, int NF, int MODE, int FLG>
__global__ __launch_bounds__(256, 2) void mm_tc(
    const float* __restrict__ A, const float* __restrict__ W,
    const float* __restrict__ bias,
    const float* __restrict__ Yi, const float* __restrict__ Zj,
    float* __restrict__ out, float* __restrict__ out2)
{
    constexpr int CH = KD / 16;
    extern __shared__ float smem_dyn[];
    float* Asm = smem_dyn;
    float* Bsm = smem_dyn + MM_ST*MM_AS;

    const int tid  = threadIdx.x;
    const int lane = tid & 31;
    const int wid  = tid >> 5;
    const int wm   = wid & 1;
    const int wn   = wid >> 1;

    const int rowBase = blockIdx.x * 128;
    const int n0 = blockIdx.y * 128;

    const float* Wp = W;
    if (MODE == 6) Wp = W + (size_t)blockIdx.z * 256 * 384;

    const int laR = tid >> 1, laK = (tid & 1) * 8;
    const int lbK = tid >> 4, lbN = (tid & 15) * 8;
    const float* Ag = A  + (size_t)(rowBase + laR) * KD + laK;
    const float* Wg = Wp + (size_t)lbK * NF + n0 + lbN;

    const unsigned sa = (unsigned)__cvta_generic_to_shared(Asm) + (laR*20 + laK)*4;
    const unsigned sb = (unsigned)__cvta_generic_to_shared(Bsm) + (lbK*132 + lbN)*4;

    #pragma unroll
    for (int s = 0; s < MM_ST-1; s++) {
        if (s < CH) {
            cp16(sa + s*MM_AS*4,      Ag + s*16);
            cp16(sa + s*MM_AS*4 + 16, Ag + s*16 + 4);
            cp16(sb + s*MM_BS*4,      Wg + (size_t)s*16*NF);
            cp16(sb + s*MM_BS*4 + 16, Wg + (size_t)s*16*NF + 4);
        }
        CP_COMMIT();
    }

    float acc[4][4][4];
    #pragma unroll
    for (int i = 0; i < 4; i++)
        #pragma unroll
        for (int j = 0; j < 4; j++)
            #pragma unroll
            for (int q = 0; q < 4; q++) acc[i][j][q] = 0.0f;

    #pragma unroll 1
    for (int c = 0; c < CH; c++) {
        CP_WAIT2();
        __syncthreads();

        if (c + MM_ST-1 < CH) {
            const int slot = (c + MM_ST-1) & (MM_ST-1);
            const int cc = c + MM_ST-1;
            cp16(sa + slot*MM_AS*4,      Ag + cc*16);
            cp16(sa + slot*MM_AS*4 + 16, Ag + cc*16 + 4);
            cp16(sb + slot*MM_BS*4,      Wg + (size_t)cc*16*NF);
            cp16(sb + slot*MM_BS*4 + 16, Wg + (size_t)cc*16*NF + 4);
        }
        CP_COMMIT();

        const unsigned* As = (const unsigned*)(Asm + (c & (MM_ST-1)) * MM_AS);
        const unsigned* Bs = (const unsigned*)(Bsm + (c & (MM_ST-1)) * MM_BS);

        #pragma unroll
        for (int kk = 0; kk < 2; kk++) {
            const int kb = kk * 8;
            unsigned a[4][4], bq[4][2];
            #pragma unroll
            for (int mt = 0; mt < 4; mt++) {
                int r0 = wm*64 + mt*16 + (lane >> 2);
                a[mt][0] = As[(r0  )*20 + kb + (lane & 3)];
                a[mt][1] = As[(r0+8)*20 + kb + (lane & 3)];
                a[mt][2] = As[(r0  )*20 + kb + (lane & 3) + 4];
                a[mt][3] = As[(r0+8)*20 + kb + (lane & 3) + 4];
            }
            #pragma unroll
            for (int nt = 0; nt < 4; nt++) {
                int cc2 = wn*32 + nt*8 + (lane >> 2);
                bq[nt][0] = Bs[(kb + (lane & 3)    )*132 + cc2];
                bq[nt][1] = Bs[(kb + (lane & 3) + 4)*132 + cc2];
            }
            #pragma unroll
            for (int mt = 0; mt < 4; mt++)
                #pragma unroll
                for (int nt = 0; nt < 4; nt++)
                    mma8(acc[mt][nt], a[mt], bq[nt]);
        }
    }

    // ---------------- epilogue ----------------
    float* sred = smem_dyn;                     // reuse pipeline smem (MODE 5)
    if (MODE == 5) __syncthreads();             // all warps done with mainloop smem

    #pragma unroll
    for (int mt = 0; mt < 4; mt++) {
        #pragma unroll
        for (int h = 0; h < 2; h++) {
            const int r = wm*64 + mt*16 + (lane >> 2) + h*8;
            const int grow = rowBase + r;

            const float* yip = nullptr; const float* zjp = nullptr;
            float mij = 0.f, dn = 1.f, mi = 0.f, cn = 0.f;
            const float* nhp = nullptr; const float* ehp = nullptr;
            if (MODE == 1 || MODE == 5) {
                int nlin = grow / KNB;
                int b = nlin >> 11;
                yip = Yi + (size_t)nlin * NF + n0;
                zjp = Zj + (size_t)(b*NN + g_eidx[grow]) * NF + n0;
                if (MODE == 5) mij = g_maskij[grow];
            } else if (MODE == 2) {
                mij = g_maskij[grow];
                ehp = g_edgeh + (size_t)grow * DE + n0;
            } else if (MODE == 3) {
                dn = g_denom[grow]; mi = g_maski[grow]; cn = g_cnt[grow];
                nhp = g_nodeh + (size_t)grow * DN + n0;
            } else if (MODE == 4) {
                mij = g_maskij[grow];
            }

            #pragma unroll
            for (int nt = 0; nt < 4; nt++) {
                const int c0 = wn*32 + nt*8 + 2*(lane & 3);
                float v0 = acc[mt][nt][h*2 + 0];
                float v1 = acc[mt][nt][h*2 + 1];
                if (MODE == 6) {
                    float* op;
                    if (n0 < 256) op = out  + (size_t)blockIdx.z*NNODE*DN + (size_t)grow*DN + n0;
                    else          op = out2 + (size_t)blockIdx.z*NNODE*DE + (size_t)grow*DE + (n0-256);
                    *(float2*)(op + c0) = make_float2(v0, v1);
                } else if (MODE == 1) {
                    float2 bsv = *(const float2*)(bias + n0 + c0);
                    float2 yv  = *(const float2*)(yip + c0);
                    float2 zv  = *(const float2*)(zjp + c0);
                    v0 = rtf(softplus_f(v0 + bsv.x + yv.x + zv.x));
                    v1 = rtf(softplus_f(v1 + bsv.y + yv.y + zv.y));
                    *(float2*)(out + (size_t)grow*NF + n0 + c0) = make_float2(v0, v1);
                } else if (MODE == 5) {
                    float2 bsv = *(const float2*)(bias + n0 + c0);
                    float2 yv  = *(const float2*)(yip + c0);
                    float2 zv  = *(const float2*)(zjp + c0);
                    v0 = softplus_f(v0 + bsv.x + yv.x + zv.x) * mij;
                    v1 = softplus_f(v1 + bsv.y + yv.y + zv.y) * mij;
                    sred[r*130 + c0]     = v0;
                    sred[r*130 + c0 + 1] = v1;
                } else if (MODE == 4) {
                    float2 bsv = *(const float2*)(bias + n0 + c0);
                    v0 = (v0 + bsv.x) * mij;
                    v1 = (v1 + bsv.y) * mij;
                    *(float2*)(out  + (size_t)grow*NF + n0 + c0) = make_float2(v0, v1);
                    *(float2*)(out2 + (size_t)grow*NF + n0 + c0) = make_float2(rtf(v0), rtf(v1));
                } else if (MODE == 2) {
                    float2 bsv = *(const float2*)(bias + n0 + c0);
                    float2 ev  = *(const float2*)(ehp + c0);
                    v0 = (ev.x + v0 + bsv.x) * mij;
                    v1 = (ev.y + v1 + bsv.y) * mij;
                    *(float2*)(out + (size_t)grow*NF + n0 + c0) = make_float2(v0, v1);
                    if (FLG) *(float2*)(out2 + (size_t)grow*NF + n0 + c0) = make_float2(rtf(v0), rtf(v1));
                } else { // MODE 3
                    float2 bsv = *(const float2*)(bias + n0 + c0);
                    float2 nv  = *(const float2*)(nhp + c0);
                    v0 = (nv.x + (v0 + cn*bsv.x) / dn) * mi;
                    v1 = (nv.y + (v1 + cn*bsv.y) / dn) * mi;
                    *(float2*)(out + (size_t)grow*NF + n0 + c0) = make_float2(v0, v1);
                    if (FLG) *(float2*)(out2 + (size_t)grow*NF + n0 + c0) = make_float2(rtf(v0), rtf(v1));
                }
            }
        }
    }

    if (MODE == 5) {
        __syncthreads();
        if (tid < 128) {
            const int c = tid;
            const int nfirst = rowBase / KNB;
            const int nlast  = (rowBase + 127) / KNB;
            for (int n = nfirst; n <= nlast; n++) {
                int r0 = n*KNB - rowBase;
                int r1 = r0 + KNB;
                r0 = r0 < 0 ? 0 : r0;
                r1 = r1 > 128 ? 128 : r1;
                float s = 0.0f;
                for (int r = r0; r < r1; r++) s += sred[r*130 + c];
                atomicAdd(&g_ksum[(size_t)n*DN + n0 + c], s);
            }
        }
    }
}

// ---------------- launch ----------------
extern "C" void kernel_launch(void* const* d_in, const int* in_sizes, int n_in,
                              void* d_out, int out_size)
{
    const float* X    = (const float*)d_in[0];
    const int*   C    = (const int*)  d_in[1];
    const float* Wn   = (const float*)d_in[2];
    const float* bn   = (const float*)d_in[3];
    const float* We   = (const float*)d_in[4];
    const float* be   = (const float*)d_in[5];
    const float* Wm1  = (const float*)d_in[6];
    const float* bm1  = (const float*)d_in[7];
    const float* Wm2  = (const float*)d_in[8];
    const float* bm2  = (const float*)d_in[9];
    const float* Wue1 = (const float*)d_in[10];
    const float* bue1 = (const float*)d_in[11];
    const float* Wue2 = (const float*)d_in[12];
    const float* bue2 = (const float*)d_in[13];
    float* out = (float*)d_out;

    cudaFuncSetAttribute(mm_tc<32, 128,4,0>, cudaFuncAttributeMaxDynamicSharedMemorySize, MM_SMEM);
    cudaFuncSetAttribute(mm_tc<256,384,6,0>, cudaFuncAttributeMaxDynamicSharedMemorySize, MM_SMEM);
    cudaFuncSetAttribute(mm_tc<128,256,5,0>, cudaFuncAttributeMaxDynamicSharedMemorySize, MM_SMEM);
    cudaFuncSetAttribute(mm_tc<128,128,1,0>, cudaFuncAttributeMaxDynamicSharedMemorySize, MM_SMEM);
    cudaFuncSetAttribute(mm_tc<256,256,3,1>, cudaFuncAttributeMaxDynamicSharedMemorySize, MM_SMEM);
    cudaFuncSetAttribute(mm_tc<256,256,3,0>, cudaFuncAttributeMaxDynamicSharedMemorySize, MM_SMEM);
    cudaFuncSetAttribute(mm_tc<128,128,2,1>, cudaFuncAttributeMaxDynamicSharedMemorySize, MM_SMEM);
    cudaFuncSetAttribute(mm_tc<128,128,2,0>, cudaFuncAttributeMaxDynamicSharedMemorySize, MM_SMEM);

    float* Ym;  cudaGetSymbolAddress((void**)&Ym,  g_Ym);
    float* Ye;  cudaGetSymbolAddress((void**)&Ye,  g_Ye);
    float* T2;  cudaGetSymbolAddress((void**)&T2,  g_t2);
    float* Eh;  cudaGetSymbolAddress((void**)&Eh,  g_edgeh);
    float* Ehr; cudaGetSymbolAddress((void**)&Ehr, g_edgehr);
    float* Nh;  cudaGetSymbolAddress((void**)&Nh,  g_nodeh);
    float* Nhr; cudaGetSymbolAddress((void**)&Nhr, g_nodehr);
    float* Ks;  cudaGetSymbolAddress((void**)&Ks,  g_ksum);
    float* Wr;  cudaGetSymbolAddress((void**)&Wr,  g_Wr);
    float* Ft;  cudaGetSymbolAddress((void**)&Ft,  g_featr);

    round_w_kernel<<<512, 256>>>(Wm1, Wue1, Wm2, Wue2, We);
    frame_kernel<<<NNODE/8, 256>>>(X, C, Wn, bn);
    knn_kernel<<<NNODE/4, 128>>>(C);
    feat_kernel<<<ETOT/128, 128>>>();
    // edge_h init as GEMM: feat[ETOT x 32] @ We[32 x 128]
    mm_tc<32, 128, 4, 0><<<dim3(ETOT/128, 1), 256, MM_SMEM>>>(
        Ft, Wr + WR_WE, be, nullptr, nullptr, Eh, Ehr);

    for (int l = 0; l < NL; l++) {
        const float* W1cat = Wr + WR_CAT + (size_t)l*2*256*384;
        const float* W1me  = Wr + WR_E1M + (size_t)l*128*256;
        const float* W1ue  = Wr + WR_E1E + (size_t)l*128*128;
        const float* Wm2l  = Wr + WR_M2  + (size_t)l*256*256;
        const float* Wue2l = Wr + WR_UE2 + (size_t)l*128*128;
        const bool last = (l == NL-1);

        zero_ksum_kernel<<<256, 256>>>();
        // node precompute (Ym + Ye fused)
        mm_tc<256, 384, 6, 0><<<dim3(NNODE/128, 3, 2), 256, MM_SMEM>>>(
            Nhr, W1cat, nullptr, nullptr, nullptr, Ym, Ye);
        // m-path stage-1 with fused masked k-reduction into g_ksum
        mm_tc<128, 256, 5, 0><<<dim3(ETOT/128, 2), 256, MM_SMEM>>>(
            Ehr, W1me, bm1 + l*DN, Ym, Ym + (size_t)NNODE*DN, nullptr, nullptr);
        // e-path stage-1 -> t2 (rounded)
        mm_tc<128, 128, 1, 0><<<dim3(ETOT/128, 1), 256, MM_SMEM>>>(
            Ehr, W1ue, bue1 + l*DE, Ye, Ye + (size_t)NNODE*DE, T2, nullptr);
        round_ksum_kernel<<<256, 256>>>();
        // node update
        if (!last)
            mm_tc<256, 256, 3, 1><<<dim3(NNODE/128, 2), 256, MM_SMEM>>>(
                Ks, Wm2l, bm2 + l*DN, nullptr, nullptr, Nh, Nhr);
        else
            mm_tc<256, 256, 3, 0><<<dim3(NNODE/128, 2), 256, MM_SMEM>>>(
                Ks, Wm2l, bm2 + l*DN, nullptr, nullptr, out, nullptr);
        // edge update
        if (!last)
            mm_tc<128, 128, 2, 1><<<dim3(ETOT/128, 1), 256, MM_SMEM>>>(
                T2, Wue2l, bue2 + l*DE, nullptr, nullptr, Eh, Ehr);
        else
            mm_tc<128, 128, 2, 0><<<dim3(ETOT/128, 1), 256, MM_SMEM>>>(
                T2, Wue2l, bue2 + l*DE, nullptr, nullptr, out + S0OUT, nullptr);
    }

    copy_tail_kernel<<<512, 256>>>(out + S0OUT + S1OUT);
}

// round 7
// speedup vs baseline: 7.1340x; 1.1977x over previous
#include <cuda_runtime.h>
#include <cuda_fp16.h>
#include <math.h>

// ---------------- problem constants ----------------
#define BB   2
#define NN   2048
#define KNB  30
#define DN   256
#define DE   128
#define NL   3
#define NFI  12
#define EFI  28
#define ETOT (BB*NN*KNB)  // 122880
#define NNODE (BB*NN)     // 4096
#define EPSF 1e-6f
#define BIGF 1e9f
#define FLTMAX 3.402823466e38f

#define S0OUT (NNODE*DN)
#define S1OUT (ETOT*DE)

// ---------------- scratch ----------------
__device__ float  g_nodeh [NNODE*DN];
__device__ __half g_nodehr[NNODE*DN];
__device__ float  g_edgeh [ETOT*DE];
__device__ __half g_edgehr[ETOT*DE];
__device__ int    g_eidx [ETOT];
__device__ float  g_maski[NNODE];
__device__ float  g_maskij[ETOT];
__device__ float  g_denom[NNODE];
__device__ float  g_cnt  [NNODE];
__device__ float  g_R  [NNODE*9];
__device__ float  g_Xc [NNODE*3];
__device__ __half g_t2h[ETOT*DE];
__device__ float  g_Ym [2*NNODE*DN];
__device__ float  g_Ye [2*NNODE*DE];
__device__ float  g_ksum [NNODE*DN];       // fp32 atomic accum
__device__ __half g_ksumh[NNODE*DN];       // rounded copy (MMA input)
__device__ __half g_featr[ETOT*32];

// transposed fp16 weight arena: W^T[n][k]
#define WT_CAT 0
#define WT_E1M (3*2*384*256)            // 589824
#define WT_E1E (WT_E1M + 3*256*128)     // 688128
#define WT_M2  (WT_E1E + 3*128*128)     // 737280
#define WT_UE2 (WT_M2  + 3*256*256)     // 933888
#define WT_WE  (WT_UE2 + 3*128*128)     // 983040
#define WT_TOT (WT_WE  + 128*32)        // 987136
__device__ __half g_Wh[WT_TOT];

__device__ __forceinline__ float softplus_f(float x) {
    return fmaxf(x, 0.0f) + log1pf(expf(-fabsf(x)));
}
__device__ __forceinline__ void mma16(float* c, const unsigned* a, const unsigned* b) {
    asm volatile(
        "mma.sync.aligned.m16n8k16.row.col.f32.f16.f16.f32 "
        "{%0,%1,%2,%3},{%4,%5,%6,%7},{%8,%9},{%0,%1,%2,%3};"
        : "+f"(c[0]), "+f"(c[1]), "+f"(c[2]), "+f"(c[3])
        : "r"(a[0]), "r"(a[1]), "r"(a[2]), "r"(a[3]), "r"(b[0]), "r"(b[1]));
}
__device__ __forceinline__ void cp16(unsigned dst, const void* src) {
    asm volatile("cp.async.cg.shared.global [%0], [%1], 16;" :: "r"(dst), "l"(src));
}
#define CP_COMMIT() asm volatile("cp.async.commit_group;")
#define CP_WAIT2()  asm volatile("cp.async.wait_group 2;")

// ---------------- 0) round + transpose + repack all weights to fp16 ----------------
__global__ void round_w_kernel(const float* __restrict__ Wm1, const float* __restrict__ Wue1,
                               const float* __restrict__ Wm2, const float* __restrict__ Wue2,
                               const float* __restrict__ We)
{
    for (int i = blockIdx.x*blockDim.x + threadIdx.x; i < WT_TOT; i += gridDim.x*blockDim.x) {
        float v;
        if (i < WT_E1M) {                       // [l][z][n<384][k<256]
            int l = i / 196608, r = i % 196608;
            int z = r / 98304,  q = r % 98304;
            int n = q / 256,    k = q % 256;
            v = (n < 256) ? Wm1 [((size_t)l*640 + z*256 + k)*256 + n]
                          : Wue1[((size_t)l*640 + z*256 + k)*128 + (n - 256)];
        } else if (i < WT_E1E) {                // [l][n<256][k<128]
            int r = i - WT_E1M;
            int l = r / 32768, q = r % 32768;
            int n = q / 128,   k = q % 128;
            v = Wm1[((size_t)l*640 + 512 + k)*256 + n];
        } else if (i < WT_M2) {                 // [l][n<128][k<128]
            int r = i - WT_E1E;
            int l = r / 16384, q = r % 16384;
            int n = q / 128,   k = q % 128;
            v = Wue1[((size_t)l*640 + 512 + k)*128 + n];
        } else if (i < WT_UE2) {                // [l][n<256][k<256]
            int r = i - WT_M2;
            int l = r / 65536, q = r % 65536;
            int n = q / 256,   k = q % 256;
            v = Wm2[((size_t)l*256 + k)*256 + n];
        } else if (i < WT_WE) {                 // [l][n<128][k<128]
            int r = i - WT_UE2;
            int l = r / 16384, q = r % 16384;
            int n = q / 128,   k = q % 128;
            v = Wue2[((size_t)l*128 + k)*128 + n];
        } else {                                // [n<128][k<32]
            int r = i - WT_WE;
            int n = r / 32, k = r % 32;
            v = (k < EFI) ? We[k*128 + n] : 0.0f;
        }
        g_Wh[i] = __float2half_rn(v);
    }
}

// ---------------- 1) per-node frame, features, node_h init ----------------
__global__ void frame_kernel(const float* __restrict__ X, const int* __restrict__ C,
                             const float* __restrict__ Wn, const float* __restrict__ bn)
{
    __shared__ float s_feat[8][12];
    __shared__ float s_mask[8];
    int warp = threadIdx.x >> 5;
    int lane = threadIdx.x & 31;
    int nlin = blockIdx.x * 8 + warp;

    if (lane == 0) {
        const float* xr = X + (size_t)nlin * 12;
        float Na[3], CA[3], Ct[3], Oa[3];
        #pragma unroll
        for (int d = 0; d < 3; d++) { Na[d]=xr[d]; CA[d]=xr[3+d]; Ct[d]=xr[6+d]; Oa[d]=xr[9+d]; }
        #pragma unroll
        for (int d = 0; d < 3; d++) {
            float s = __fadd_rn(__fadd_rn(__fadd_rn(Na[d], CA[d]), Ct[d]), Oa[d]);
            g_Xc[nlin*3 + d] = __fmul_rn(s, 0.25f);
        }
        float b1[3], b2[3], b3[3], v0[3];
        #pragma unroll
        for (int d = 0; d < 3; d++) {
            b1[d] = CA[d] - Na[d];
            b2[d] = Ct[d] - CA[d];
            b3[d] = Oa[d] - Ct[d];
            v0[d] = Na[d] - CA[d];
        }
        float nb2 = sqrtf(b2[0]*b2[0] + b2[1]*b2[1] + b2[2]*b2[2]);
        float u[3];
        #pragma unroll
        for (int d = 0; d < 3; d++) u[d] = b2[d] / (nb2 + EPSF);
        float dotv = v0[0]*u[0] + v0[1]*u[1] + v0[2]*u[2];
        float t[3];
        #pragma unroll
        for (int d = 0; d < 3; d++) t[d] = v0[d] - dotv * u[d];
        float nt = sqrtf(t[0]*t[0] + t[1]*t[1] + t[2]*t[2]);
        float v[3];
        #pragma unroll
        for (int d = 0; d < 3; d++) v[d] = t[d] / (nt + EPSF);
        float w[3];
        w[0] = u[1]*v[2] - u[2]*v[1];
        w[1] = u[2]*v[0] - u[0]*v[2];
        w[2] = u[0]*v[1] - u[1]*v[0];
        #pragma unroll
        for (int d = 0; d < 3; d++) {
            g_R[nlin*9 + d*3 + 0] = u[d];
            g_R[nlin*9 + d*3 + 1] = v[d];
            g_R[nlin*9 + d*3 + 2] = w[d];
        }
        float nb1 = sqrtf(b1[0]*b1[0] + b1[1]*b1[1] + b1[2]*b1[2]);
        float nb3 = sqrtf(b3[0]*b3[0] + b3[1]*b3[1] + b3[2]*b3[2]);
        #pragma unroll
        for (int d = 0; d < 3; d++) {
            s_feat[warp][0 + d] = b1[d] / (nb1 + EPSF);
            s_feat[warp][4 + d] = b2[d] / (nb2 + EPSF);
            s_feat[warp][8 + d] = b3[d] / (nb3 + EPSF);
        }
        s_feat[warp][3]  = logf(nb1 + EPSF);
        s_feat[warp][7]  = logf(nb2 + EPSF);
        s_feat[warp][11] = logf(nb3 + EPSF);
        float mk = (C[nlin] > 0) ? 1.0f : 0.0f;
        s_mask[warp] = mk;
        g_maski[nlin] = mk;
    }
    __syncwarp();

    float f[12];
    #pragma unroll
    for (int i = 0; i < 12; i++) f[i] = s_feat[warp][i];
    float mk = s_mask[warp];
    #pragma unroll
    for (int r = 0; r < 8; r++) {
        int c = lane + r * 32;
        float acc = bn[c];
        #pragma unroll
        for (int ff = 0; ff < NFI; ff++) acc += f[ff] * Wn[ff*DN + c];
        float v = acc * mk;
        g_nodeh [(size_t)nlin*DN + c] = v;
        g_nodehr[(size_t)nlin*DN + c] = __float2half_rn(v);
    }
}

// ---------------- 2) kNN: warp-per-node, exact semantics ----------------
__global__ __launch_bounds__(128) void knn_kernel(const int* __restrict__ C)
{
    __shared__ float s_d2[4][NN];
    int wid = threadIdx.x >> 5;
    int lane = threadIdx.x & 31;
    int nlin = blockIdx.x * 4 + wid;
    int b = nlin >> 11;
    int n = nlin & (NN - 1);

    float xi0 = g_Xc[nlin*3+0], xi1 = g_Xc[nlin*3+1], xi2 = g_Xc[nlin*3+2];
    const int* Cb = C + b*NN;
    for (int j = lane; j < NN; j += 32) {
        float dx = __fadd_rn(xi0, -g_Xc[(size_t)(b*NN + j)*3 + 0]);
        float dy = __fadd_rn(xi1, -g_Xc[(size_t)(b*NN + j)*3 + 1]);
        float dz = __fadd_rn(xi2, -g_Xc[(size_t)(b*NN + j)*3 + 2]);
        float d2 = __fadd_rn(__fadd_rn(__fmul_rn(dx,dx), __fmul_rn(dy,dy)), __fmul_rn(dz,dz));
        if (Cb[j] <= 0) d2 = __fadd_rn(d2, BIGF);
        if (j == n)     d2 = __fadd_rn(d2, BIGF);
        s_d2[wid][j] = d2;
    }
    __syncwarp();

    float mi = g_maski[nlin];
    float cnt = 0.0f;
    for (int kk = 0; kk < KNB; kk++) {
        float bv = FLTMAX; int bi = 0x7fffffff;
        #pragma unroll 4
        for (int j = lane; j < NN; j += 32) {
            float v = s_d2[wid][j];
            if (v < bv || (v == bv && j < bi)) { bv = v; bi = j; }
        }
        #pragma unroll
        for (int off = 16; off > 0; off >>= 1) {
            float v2 = __shfl_down_sync(0xffffffffu, bv, off);
            int   i2 = __shfl_down_sync(0xffffffffu, bi, off);
            if (v2 < bv || (v2 == bv && i2 < bi)) { bv = v2; bi = i2; }
        }
        bi = __shfl_sync(0xffffffffu, bi, 0);
        if (lane == 0) {
            int e = nlin*KNB + kk;
            g_eidx[e] = bi;
            float mj = (Cb[bi] > 0) ? 1.0f : 0.0f;
            float mij = mi * mj;
            g_maskij[e] = mij;
            cnt += mij;
            s_d2[wid][bi] = FLTMAX;
        }
        __syncwarp();
    }
    if (lane == 0) { g_cnt[nlin] = cnt; g_denom[nlin] = cnt + EPSF; }
}

// ---------------- 3) edge features -> g_featr (fp16, padded to 32) ----------------
__global__ __launch_bounds__(128) void feat_kernel()
{
    int e = blockIdx.x * 128 + threadIdx.x;
    int nlin = e / KNB;
    int b = nlin >> 11;
    int j = g_eidx[e];
    int jl = b*NN + j;

    float dv[3];
    #pragma unroll
    for (int d = 0; d < 3; d++) dv[d] = g_Xc[jl*3+d] - g_Xc[nlin*3+d];
    float dist = sqrtf(dv[0]*dv[0] + dv[1]*dv[1] + dv[2]*dv[2]);
    float Ri[9], Rj[9];
    #pragma unroll
    for (int q = 0; q < 9; q++) { Ri[q] = g_R[nlin*9+q]; Rj[q] = g_R[jl*9+q]; }

    float f[32];
    #pragma unroll
    for (int mc = 0; mc < 16; mc++) {
        float cm = (float)(20.0 * mc / 15.0);
        float z = (dist - cm) * 0.8f;
        f[mc] = expf(-z*z);
    }
    float inv = 1.0f / (dist + EPSF);
    #pragma unroll
    for (int c = 0; c < 3; c++) {
        float loc = Ri[0*3+c]*dv[0] + Ri[1*3+c]*dv[1] + Ri[2*3+c]*dv[2];
        f[16 + c] = loc * inv;
    }
    #pragma unroll
    for (int ee = 0; ee < 3; ee++)
        #pragma unroll
        for (int ff = 0; ff < 3; ff++)
            f[19 + ee*3 + ff] = Ri[0*3+ee]*Rj[0*3+ff] + Ri[1*3+ee]*Rj[1*3+ff] + Ri[2*3+ee]*Rj[2*3+ff];
    f[28] = f[29] = f[30] = f[31] = 0.0f;

    __half2* op = (__half2*)(g_featr + (size_t)e*32);
    #pragma unroll
    for (int q = 0; q < 16; q++)
        op[q] = __floats2half2_rn(f[2*q], f[2*q+1]);
}

// ---------------- helpers ----------------
__global__ void zero_ksum_kernel()
{
    float4* p = (float4*)g_ksum;
    for (int i = blockIdx.x*blockDim.x + threadIdx.x; i < NNODE*DN/4; i += gridDim.x*blockDim.x)
        p[i] = make_float4(0.f, 0.f, 0.f, 0.f);
}
__global__ void round_ksum_kernel()
{
    for (int i = blockIdx.x*blockDim.x + threadIdx.x; i < NNODE*DN; i += gridDim.x*blockDim.x)
        g_ksumh[i] = __float2half_rn(g_ksum[i]);
}
__global__ void copy_tail_kernel(float* __restrict__ out)
{
    const int S2 = ETOT, S3 = NNODE;
    const int TOT = ETOT + NNODE + ETOT;
    for (int i = blockIdx.x*blockDim.x + threadIdx.x; i < TOT; i += gridDim.x*blockDim.x) {
        float v;
        if (i < S2)           v = (float)g_eidx[i];
        else if (i < S2+S3)   v = g_maski[i - S2];
        else                  v = g_maskij[i - S2 - S3];
        out[i] = v;
    }
}

// ---------------- 4) fp16 TC GEMM (m16n8k16), 4-stage cp.async ----------------
// A [M x KD] fp16 row-major; W = W^T [NF x KD] fp16 (n-major). Acc fp32.
// MODE 1: t2h = h(softplus(A@W + bias + Yi + Zj))
// MODE 2: edge_h = (edge_h + A@W + bias)*maskij  [FLG: + fp16 shadow]
// MODE 3: node_h = (node_h + (A@W + cnt*bias)/denom)*mask_i [FLG: + shadow]
// MODE 4: edge_h init = (A@W + bias)*maskij -> out fp32 + outh fp16
// MODE 5: m-path stage-1: masked softplus -> smem reduce -> atomic g_ksum
// MODE 6: node precompute cat: cols<256 -> out(Ym)[z], cols>=256 -> out2(Ye)[z]
#define MM_ST 4
#define MM_AS (128*24)                    // halfs per A stage (pad 16->24)
#define MM_BS (128*24)                    // halfs per B stage
#define MM_SMEM 66560                     // max(4*(AS+BS)*2 = 49152, 128*130*4)

template<int KD, int NF, int MODE, int FLG>
__global__ __launch_bounds__(256, 2) void mm_tc(
    const __half* __restrict__ A, const __half* __restrict__ W,
    const float* __restrict__ bias,
    const float* __restrict__ Yi, const float* __restrict__ Zj,
    float* __restrict__ out, float* __restrict__ out2, __half* __restrict__ outh)
{
    constexpr int CH = KD / 16;
    extern __shared__ float smem_dyn[];
    __half* Asm = (__half*)smem_dyn;
    __half* Bsm = Asm + MM_ST*MM_AS;

    const int tid  = threadIdx.x;
    const int lane = tid & 31;
    const int wid  = tid >> 5;
    const int wm   = wid & 1;
    const int wn   = wid >> 1;

    const int rowBase = blockIdx.x * 128;
    const int n0 = blockIdx.y * 128;

    const __half* Wp = W;
    if (MODE == 6) Wp = W + (size_t)blockIdx.z * 384 * 256;

    const int laR = tid >> 1, laK = (tid & 1) * 8;
    const __half* Ag = A  + (size_t)(rowBase + laR) * KD + laK;
    const __half* Wg = Wp + (size_t)(n0 + laR) * KD + laK;

    const unsigned sa = (unsigned)__cvta_generic_to_shared(Asm) + (laR*24 + laK)*2;
    const unsigned sb = (unsigned)__cvta_generic_to_shared(Bsm) + (laR*24 + laK)*2;

    #pragma unroll
    for (int s = 0; s < MM_ST-1; s++) {
        if (s < CH) {
            cp16(sa + s*MM_AS*2, Ag + s*16);
            cp16(sb + s*MM_BS*2, Wg + s*16);
        }
        CP_COMMIT();
    }

    float acc[4][4][4];
    #pragma unroll
    for (int i = 0; i < 4; i++)
        #pragma unroll
        for (int j = 0; j < 4; j++)
            #pragma unroll
            for (int q = 0; q < 4; q++) acc[i][j][q] = 0.0f;

    #pragma unroll 1
    for (int c = 0; c < CH; c++) {
        CP_WAIT2();
        __syncthreads();

        if (c + MM_ST-1 < CH) {
            const int slot = (c + MM_ST-1) & (MM_ST-1);
            const int cc = c + MM_ST-1;
            cp16(sa + slot*MM_AS*2, Ag + cc*16);
            cp16(sb + slot*MM_BS*2, Wg + cc*16);
        }
        CP_COMMIT();

        const __half* As = Asm + (c & (MM_ST-1)) * MM_AS;
        const __half* Bs = Bsm + (c & (MM_ST-1)) * MM_BS;

        unsigned a[4][4], bq[4][2];
        #pragma unroll
        for (int mt = 0; mt < 4; mt++) {
            int r0 = wm*64 + mt*16 + (lane >> 2);
            int base = r0*24 + (lane & 3)*2;
            a[mt][0] = *(const unsigned*)(As + base);
            a[mt][1] = *(const unsigned*)(As + base + 8*24);
            a[mt][2] = *(const unsigned*)(As + base + 8);
            a[mt][3] = *(const unsigned*)(As + base + 8*24 + 8);
        }
        #pragma unroll
        for (int nt = 0; nt < 4; nt++) {
            int nn = wn*32 + nt*8 + (lane >> 2);
            int nb = nn*24 + (lane & 3)*2;
            bq[nt][0] = *(const unsigned*)(Bs + nb);
            bq[nt][1] = *(const unsigned*)(Bs + nb + 8);
        }
        #pragma unroll
        for (int mt = 0; mt < 4; mt++)
            #pragma unroll
            for (int nt = 0; nt < 4; nt++)
                mma16(acc[mt][nt], a[mt], bq[nt]);
    }

    // ---------------- epilogue ----------------
    float* sred = smem_dyn;
    if (MODE == 5) __syncthreads();

    #pragma unroll
    for (int mt = 0; mt < 4; mt++) {
        #pragma unroll
        for (int h = 0; h < 2; h++) {
            const int r = wm*64 + mt*16 + (lane >> 2) + h*8;
            const int grow = rowBase + r;

            const float* yip = nullptr; const float* zjp = nullptr;
            float mij = 0.f, dn = 1.f, mi = 0.f, cn = 0.f;
            const float* nhp = nullptr; const float* ehp = nullptr;
            if (MODE == 1 || MODE == 5) {
                int nlin = grow / KNB;
                int b = nlin >> 11;
                yip = Yi + (size_t)nlin * NF + n0;
                zjp = Zj + (size_t)(b*NN + g_eidx[grow]) * NF + n0;
                if (MODE == 5) mij = g_maskij[grow];
            } else if (MODE == 2) {
                mij = g_maskij[grow];
                ehp = g_edgeh + (size_t)grow * DE + n0;
            } else if (MODE == 3) {
                dn = g_denom[grow]; mi = g_maski[grow]; cn = g_cnt[grow];
                nhp = g_nodeh + (size_t)grow * DN + n0;
            } else if (MODE == 4) {
                mij = g_maskij[grow];
            }

            #pragma unroll
            for (int nt = 0; nt < 4; nt++) {
                const int c0 = wn*32 + nt*8 + 2*(lane & 3);
                float v0 = acc[mt][nt][h*2 + 0];
                float v1 = acc[mt][nt][h*2 + 1];
                if (MODE == 6) {
                    float* op;
                    if (n0 < 256) op = out  + (size_t)blockIdx.z*NNODE*DN + (size_t)grow*DN + n0;
                    else          op = out2 + (size_t)blockIdx.z*NNODE*DE + (size_t)grow*DE + (n0-256);
                    *(float2*)(op + c0) = make_float2(v0, v1);
                } else if (MODE == 1) {
                    float2 bsv = *(const float2*)(bias + n0 + c0);
                    float2 yv  = *(const float2*)(yip + c0);
                    float2 zv  = *(const float2*)(zjp + c0);
                    v0 = softplus_f(v0 + bsv.x + yv.x + zv.x);
                    v1 = softplus_f(v1 + bsv.y + yv.y + zv.y);
                    *(__half2*)(outh + (size_t)grow*NF + n0 + c0) = __floats2half2_rn(v0, v1);
                } else if (MODE == 5) {
                    float2 bsv = *(const float2*)(bias + n0 + c0);
                    float2 yv  = *(const float2*)(yip + c0);
                    float2 zv  = *(const float2*)(zjp + c0);
                    v0 = softplus_f(v0 + bsv.x + yv.x + zv.x) * mij;
                    v1 = softplus_f(v1 + bsv.y + yv.y + zv.y) * mij;
                    sred[r*130 + c0]     = v0;
                    sred[r*130 + c0 + 1] = v1;
                } else if (MODE == 4) {
                    float2 bsv = *(const float2*)(bias + n0 + c0);
                    v0 = (v0 + bsv.x) * mij;
                    v1 = (v1 + bsv.y) * mij;
                    *(float2*)(out + (size_t)grow*NF + n0 + c0) = make_float2(v0, v1);
                    *(__half2*)(outh + (size_t)grow*NF + n0 + c0) = __floats2half2_rn(v0, v1);
                } else if (MODE == 2) {
                    float2 bsv = *(const float2*)(bias + n0 + c0);
                    float2 ev  = *(const float2*)(ehp + c0);
                    v0 = (ev.x + v0 + bsv.x) * mij;
                    v1 = (ev.y + v1 + bsv.y) * mij;
                    *(float2*)(out + (size_t)grow*NF + n0 + c0) = make_float2(v0, v1);
                    if (FLG) *(__half2*)(outh + (size_t)grow*NF + n0 + c0) = __floats2half2_rn(v0, v1);
                } else { // MODE 3
                    float2 bsv = *(const float2*)(bias + n0 + c0);
                    float2 nv  = *(const float2*)(nhp + c0);
                    v0 = (nv.x + (v0 + cn*bsv.x) / dn) * mi;
                    v1 = (nv.y + (v1 + cn*bsv.y) / dn) * mi;
                    *(float2*)(out + (size_t)grow*NF + n0 + c0) = make_float2(v0, v1);
                    if (FLG) *(__half2*)(outh + (size_t)grow*NF + n0 + c0) = __floats2half2_rn(v0, v1);
                }
            }
        }
    }

    if (MODE == 5) {
        __syncthreads();
        if (tid < 128) {
            const int c = tid;
            const int nfirst = rowBase / KNB;
            const int nlast  = (rowBase + 127) / KNB;
            for (int n = nfirst; n <= nlast; n++) {
                int r0 = n*KNB - rowBase;
                int r1 = r0 + KNB;
                r0 = r0 < 0 ? 0 : r0;
                r1 = r1 > 128 ? 128 : r1;
                float s = 0.0f;
                for (int r = r0; r < r1; r++) s += sred[r*130 + c];
                atomicAdd(&g_ksum[(size_t)n*DN + n0 + c], s);
            }
        }
    }
}

// ---------------- launch ----------------
extern "C" void kernel_launch(void* const* d_in, const int* in_sizes, int n_in,
                              void* d_out, int out_size)
{
    const float* X    = (const float*)d_in[0];
    const int*   C    = (const int*)  d_in[1];
    const float* Wn   = (const float*)d_in[2];
    const float* bn   = (const float*)d_in[3];
    const float* We   = (const float*)d_in[4];
    const float* be   = (const float*)d_in[5];
    const float* Wm1  = (const float*)d_in[6];
    const float* bm1  = (const float*)d_in[7];
    const float* Wm2  = (const float*)d_in[8];
    const float* bm2  = (const float*)d_in[9];
    const float* Wue1 = (const float*)d_in[10];
    const float* bue1 = (const float*)d_in[11];
    const float* Wue2 = (const float*)d_in[12];
    const float* bue2 = (const float*)d_in[13];
    float* out = (float*)d_out;

    cudaFuncSetAttribute(mm_tc<32, 128,4,0>, cudaFuncAttributeMaxDynamicSharedMemorySize, MM_SMEM);
    cudaFuncSetAttribute(mm_tc<256,384,6,0>, cudaFuncAttributeMaxDynamicSharedMemorySize, MM_SMEM);
    cudaFuncSetAttribute(mm_tc<128,256,5,0>, cudaFuncAttributeMaxDynamicSharedMemorySize, MM_SMEM);
    cudaFuncSetAttribute(mm_tc<128,128,1,0>, cudaFuncAttributeMaxDynamicSharedMemorySize, MM_SMEM);
    cudaFuncSetAttribute(mm_tc<256,256,3,1>, cudaFuncAttributeMaxDynamicSharedMemorySize, MM_SMEM);
    cudaFuncSetAttribute(mm_tc<256,256,3,0>, cudaFuncAttributeMaxDynamicSharedMemorySize, MM_SMEM);
    cudaFuncSetAttribute(mm_tc<128,128,2,1>, cudaFuncAttributeMaxDynamicSharedMemorySize, MM_SMEM);
    cudaFuncSetAttribute(mm_tc<128,128,2,0>, cudaFuncAttributeMaxDynamicSharedMemorySize, MM_SMEM);

    float*  Ym;  cudaGetSymbolAddress((void**)&Ym,  g_Ym);
    float*  Ye;  cudaGetSymbolAddress((void**)&Ye,  g_Ye);
    __half* T2;  cudaGetSymbolAddress((void**)&T2,  g_t2h);
    float*  Eh;  cudaGetSymbolAddress((void**)&Eh,  g_edgeh);
    __half* Ehr; cudaGetSymbolAddress((void**)&Ehr, g_edgehr);
    float*  Nh;  cudaGetSymbolAddress((void**)&Nh,  g_nodeh);
    __half* Nhr; cudaGetSymbolAddress((void**)&Nhr, g_nodehr);
    __half* Ksh; cudaGetSymbolAddress((void**)&Ksh, g_ksumh);
    __half* Wh;  cudaGetSymbolAddress((void**)&Wh,  g_Wh);
    __half* Ft;  cudaGetSymbolAddress((void**)&Ft,  g_featr);

    round_w_kernel<<<512, 256>>>(Wm1, Wue1, Wm2, Wue2, We);
    frame_kernel<<<NNODE/8, 256>>>(X, C, Wn, bn);
    knn_kernel<<<NNODE/4, 128>>>(C);
    feat_kernel<<<ETOT/128, 128>>>();
    // edge_h init as GEMM: feat[ETOT x 32] @ We[32 x 128]
    mm_tc<32, 128, 4, 0><<<dim3(ETOT/128, 1), 256, MM_SMEM>>>(
        Ft, Wh + WT_WE, be, nullptr, nullptr, Eh, nullptr, Ehr);

    for (int l = 0; l < NL; l++) {
        const __half* W1cat = Wh + WT_CAT + (size_t)l*2*384*256;
        const __half* W1me  = Wh + WT_E1M + (size_t)l*256*128;
        const __half* W1ue  = Wh + WT_E1E + (size_t)l*128*128;
        const __half* Wm2l  = Wh + WT_M2  + (size_t)l*256*256;
        const __half* Wue2l = Wh + WT_UE2 + (size_t)l*128*128;
        const bool last = (l == NL-1);

        zero_ksum_kernel<<<256, 256>>>();
        // node precompute (Ym + Ye fused)
        mm_tc<256, 384, 6, 0><<<dim3(NNODE/128, 3, 2), 256, MM_SMEM>>>(
            Nhr, W1cat, nullptr, nullptr, nullptr, Ym, Ye, nullptr);
        // m-path stage-1 with fused masked k-reduction into g_ksum
        mm_tc<128, 256, 5, 0><<<dim3(ETOT/128, 2), 256, MM_SMEM>>>(
            Ehr, W1me, bm1 + l*DN, Ym, Ym + (size_t)NNODE*DN, nullptr, nullptr, nullptr);
        // e-path stage-1 -> t2h
        mm_tc<128, 128, 1, 0><<<dim3(ETOT/128, 1), 256, MM_SMEM>>>(
            Ehr, W1ue, bue1 + l*DE, Ye, Ye + (size_t)NNODE*DE, nullptr, nullptr, T2);
        round_ksum_kernel<<<256, 256>>>();
        // node update
        if (!last)
            mm_tc<256, 256, 3, 1><<<dim3(NNODE/128, 2), 256, MM_SMEM>>>(
                Ksh, Wm2l, bm2 + l*DN, nullptr, nullptr, Nh, nullptr, Nhr);
        else
            mm_tc<256, 256, 3, 0><<<dim3(NNODE/128, 2), 256, MM_SMEM>>>(
                Ksh, Wm2l, bm2 + l*DN, nullptr, nullptr, out, nullptr, nullptr);
        // edge update
        if (!last)
            mm_tc<128, 128, 2, 1><<<dim3(ETOT/128, 1), 256, MM_SMEM>>>(
                T2, Wue2l, bue2 + l*DE, nullptr, nullptr, Eh, nullptr, Ehr);
        else
            mm_tc<128, 128, 2, 0><<<dim3(ETOT/128, 1), 256, MM_SMEM>>>(
                T2, Wue2l, bue2 + l*DE, nullptr, nullptr, out + S0OUT, nullptr, nullptr);
    }

    copy_tail_kernel<<<512, 256>>>(out + S0OUT + S1OUT);
}